// round 4
// baseline (speedup 1.0000x reference)
#include <cuda_runtime.h>
#include <cuda_bf16.h>
#include <cstdint>

// Problem constants
#define BB 32
#define NN 1024
#define FF 64
#define TT 64

typedef unsigned long long ull;

// ---------------- scratch (device globals: no allocation allowed) ------------
__device__ float g_lhs[BB * NN * TT];                 // 8 MB  (b,n,t)
__device__ float g_rhs[BB * NN * TT];                 // 8 MB  (b,m,t)
__device__ float g_sig[(size_t)BB * NN * NN];         // 128 MB (b,j,m)
__device__ float g_cmax[BB * NN];                     // per-(b,m) col max
__device__ float g_csum[BB * NN];                     // per-(b,m) col sum

// ---------------- f32x2 packed-FMA helpers (sm_100a FFMA2) -------------------
__device__ __forceinline__ ull ffma2(ull a, ull b, ull c) {
    ull d;
    asm("fma.rn.f32x2 %0, %1, %2, %3;" : "=l"(d) : "l"(a), "l"(b), "l"(c));
    return d;
}
__device__ __forceinline__ ull pack2(float a) {
    ull d;
    asm("mov.b64 %0, {%1, %1};" : "=l"(d) : "f"(a));
    return d;
}
__device__ __forceinline__ float2 unpack2(ull v) {
    float2 r;
    asm("mov.b64 {%0, %1}, %2;" : "=f"(r.x), "=f"(r.y) : "l"(v));
    return r;
}

// =============================================================================
// Kernel 1: prep — lhs[b,n,t'] = sum_f (sum_t x[b,n,f,t] W1[t]) W2[f,t']
//                  rhs[b,n,t]  = sum_f W3[f] x[b,n,f,t]
// One block per (b,n) tile of x (64x64 = 16 KB). HBM-bound (512 MB read).
// =============================================================================
__global__ __launch_bounds__(64) void prep_kernel(
    const float* __restrict__ x, const float* __restrict__ W1,
    const float* __restrict__ W2, const float* __restrict__ W3)
{
    __shared__ float sx[64][65];   // pad 65 -> conflict-free both row & col reads
    __shared__ float l1[64];
    __shared__ float sW1[64], sW3[64];

    const int t = threadIdx.x;     // 0..63
    sW1[t] = W1[t];
    sW3[t] = W3[t];

    const float4* x4 = reinterpret_cast<const float4*>(x) + (size_t)blockIdx.x * 1024;
#pragma unroll
    for (int i = 0; i < 16; i++) {
        int idx = i * 64 + t;              // 0..1023 float4s
        float4 v = x4[idx];
        int f = idx >> 4;
        int c = (idx & 15) * 4;
        sx[f][c + 0] = v.x; sx[f][c + 1] = v.y;
        sx[f][c + 2] = v.z; sx[f][c + 3] = v.w;
    }
    __syncthreads();

    // lhs1[f] = dot(x[f,:], W1)   (thread t plays role f; row reads, stride-65)
    float acc = 0.f;
#pragma unroll
    for (int k = 0; k < 64; k++) acc += sx[t][k] * sW1[k];
    l1[t] = acc;

    // rhs[t] = sum_f W3[f] x[f,t]  (column reads, conflict-free via pad)
    float r = 0.f;
#pragma unroll
    for (int f = 0; f < 64; f++) r += sW3[f] * sx[f][t];

    __syncthreads();   // l1 ready

    // lhs[t] = sum_f l1[f] * W2[f,t]
    float l = 0.f;
#pragma unroll
    for (int f = 0; f < 64; f++) l += l1[f] * W2[f * 64 + t];

    size_t o = (size_t)blockIdx.x * 64 + t;
    g_lhs[o] = l;
    g_rhs[o] = r;
}

// =============================================================================
// Kernel 2: product + sigmoid.
// G[b,n,m] = sigmoid( dot(lhs[b,n,:], rhs[b,m,:]) + bs[n,m] )
// 128x128 tile per block, K=64 in 4 chunks of 16. f32x2 microkernel.
// =============================================================================
__global__ __launch_bounds__(256, 2) void product_kernel(
    const float* __restrict__ bs)
{
    __shared__ __align__(16) float Ls[16][132];   // [k][n]
    __shared__ __align__(16) float Rs[16][132];   // [k][m]

    const int tid = threadIdx.x;
    const int b  = blockIdx.z;
    const int n0 = blockIdx.y * 128;
    const int m0 = blockIdx.x * 128;

    const float* L = g_lhs + ((size_t)b * NN + n0) * TT;
    const float* R = g_rhs + ((size_t)b * NN + m0) * TT;

    const int i0 = (tid >> 4) * 8;     // row group within tile
    const int j0 = (tid & 15) * 8;     // col group within tile

    ull acc[8][4];
#pragma unroll
    for (int ii = 0; ii < 8; ii++)
#pragma unroll
        for (int jj = 0; jj < 4; jj++) acc[ii][jj] = 0ull;

#pragma unroll 1
    for (int kt = 0; kt < 4; kt++) {
        const int k0 = kt * 16;
        __syncthreads();
#pragma unroll
        for (int rr = 0; rr < 2; rr++) {
            int g = tid + 256 * rr;
            int row = g >> 2;
            int c = (g & 3) * 4;
            float4 va = *(const float4*)(L + (size_t)row * TT + k0 + c);
            float4 vb = *(const float4*)(R + (size_t)row * TT + k0 + c);
            Ls[c + 0][row] = va.x; Ls[c + 1][row] = va.y;
            Ls[c + 2][row] = va.z; Ls[c + 3][row] = va.w;
            Rs[c + 0][row] = vb.x; Rs[c + 1][row] = vb.y;
            Rs[c + 2][row] = vb.z; Rs[c + 3][row] = vb.w;
        }
        __syncthreads();
#pragma unroll
        for (int k = 0; k < 16; k++) {
            float a[8];
            ull bv[4];
#pragma unroll
            for (int ii = 0; ii < 8; ii++) a[ii] = Ls[k][i0 + ii];
#pragma unroll
            for (int jj = 0; jj < 4; jj++)
                bv[jj] = *(const ull*)&Rs[k][j0 + jj * 2];
#pragma unroll
            for (int ii = 0; ii < 8; ii++) {
                ull ap = pack2(a[ii]);
#pragma unroll
                for (int jj = 0; jj < 4; jj++)
                    acc[ii][jj] = ffma2(ap, bv[jj], acc[ii][jj]);
            }
        }
    }

    // epilogue: + bs, sigmoid, store
    float* Sg = g_sig + (size_t)b * NN * NN;
#pragma unroll
    for (int ii = 0; ii < 8; ii++) {
        int n = n0 + i0 + ii;
#pragma unroll
        for (int jj = 0; jj < 4; jj++) {
            int m = m0 + j0 + jj * 2;
            float2 p = unpack2(acc[ii][jj]);
            float2 bb = *(const float2*)&bs[(size_t)n * NN + m];
            float2 o;
            o.x = 1.f / (1.f + __expf(-(p.x + bb.x)));
            o.y = 1.f / (1.f + __expf(-(p.y + bb.y)));
            *(float2*)&Sg[(size_t)n * NN + m] = o;
        }
    }
}

// =============================================================================
// Kernel 3: the dominant GEMM.  S[b,i,m] = sum_j Vs[i,j] * G[b,j,m]
// 128x128x16 tiles, K=1024 (64 iters), register-prefetch double buffering,
// f32x2 packed FMA (32 FFMA2 per thread per k). Writes raw S to d_out.
// =============================================================================
__global__ __launch_bounds__(256, 2) void gemm_kernel(
    const float* __restrict__ Vs, float* __restrict__ S)
{
    __shared__ __align__(16) float As[16][132];   // [k][i]   (Vs tile, transposed)
    __shared__ __align__(16) float Bs[16][132];   // [k][m]   (G tile)

    const int tid = threadIdx.x;
    const int b   = blockIdx.z;
    const int i0g = blockIdx.y * 128;
    const int m0  = blockIdx.x * 128;

    const float* Gb = g_sig + (size_t)b * NN * NN;

    const int i0 = (tid >> 4) * 8;
    const int j0 = (tid & 15) * 8;

    // loader decompositions (fixed per thread)
    const int a_row = (tid >> 2);            // 0..63   (g = tid + 256*r -> row = g>>2)
    const int a_c   = (tid & 3) * 4;
    const int b_kr  = (tid >> 5);            // 0..7
    const int b_c   = (tid & 31) * 4;

    ull acc[8][4];
#pragma unroll
    for (int ii = 0; ii < 8; ii++)
#pragma unroll
        for (int jj = 0; jj < 4; jj++) acc[ii][jj] = 0ull;

    float4 ra[2], rb[2];
    // prefetch k0 = 0
#pragma unroll
    for (int rr = 0; rr < 2; rr++) {
        ra[rr] = *(const float4*)(Vs + (size_t)(i0g + a_row + 64 * rr) * NN + a_c);
        rb[rr] = *(const float4*)(Gb + (size_t)(b_kr + 8 * rr) * NN + m0 + b_c);
    }

#pragma unroll 1
    for (int kt = 0; kt < 64; kt++) {
        // store current tiles to smem
#pragma unroll
        for (int rr = 0; rr < 2; rr++) {
            int row = a_row + 64 * rr;
            As[a_c + 0][row] = ra[rr].x; As[a_c + 1][row] = ra[rr].y;
            As[a_c + 2][row] = ra[rr].z; As[a_c + 3][row] = ra[rr].w;
            *(float4*)&Bs[b_kr + 8 * rr][b_c] = rb[rr];
        }
        __syncthreads();

        // prefetch next k-chunk while computing this one
        if (kt < 63) {
            int k0 = (kt + 1) * 16;
#pragma unroll
            for (int rr = 0; rr < 2; rr++) {
                ra[rr] = *(const float4*)(Vs + (size_t)(i0g + a_row + 64 * rr) * NN + k0 + a_c);
                rb[rr] = *(const float4*)(Gb + (size_t)(k0 + b_kr + 8 * rr) * NN + m0 + b_c);
            }
        }

#pragma unroll
        for (int k = 0; k < 16; k++) {
            float a[8];
            ull bv[4];
#pragma unroll
            for (int ii = 0; ii < 8; ii++) a[ii] = As[k][i0 + ii];
#pragma unroll
            for (int jj = 0; jj < 4; jj++)
                bv[jj] = *(const ull*)&Bs[k][j0 + jj * 2];
#pragma unroll
            for (int ii = 0; ii < 8; ii++) {
                ull ap = pack2(a[ii]);
#pragma unroll
                for (int jj = 0; jj < 4; jj++)
                    acc[ii][jj] = ffma2(ap, bv[jj], acc[ii][jj]);
            }
        }
        __syncthreads();
    }

    float* Sb = S + (size_t)b * NN * NN;
#pragma unroll
    for (int ii = 0; ii < 8; ii++) {
        size_t rowbase = (size_t)(i0g + i0 + ii) * NN + m0 + j0;
#pragma unroll
        for (int jj = 0; jj < 4; jj++)
            *(ull*)&Sb[rowbase + jj * 2] = acc[ii][jj];
    }
}

// =============================================================================
// Kernel 4: per-(b,m) column online max + exp-sum (softmax over axis i).
// 512 blocks x 64 threads; m contiguous -> coalesced 128 MB read.
// =============================================================================
__global__ __launch_bounds__(64) void colstats_kernel(const float* __restrict__ S)
{
    const int blk = blockIdx.x;                 // 0..511
    const int b = blk >> 4;
    const int m = ((blk & 15) << 6) + threadIdx.x;
    const float* p = S + (size_t)b * NN * NN + m;

    float mx[4] = {-1e30f, -1e30f, -1e30f, -1e30f};
    float sm[4] = {0.f, 0.f, 0.f, 0.f};

#pragma unroll 2
    for (int i = 0; i < 1024; i += 4) {
        float v0 = p[(size_t)(i + 0) << 10];
        float v1 = p[(size_t)(i + 1) << 10];
        float v2 = p[(size_t)(i + 2) << 10];
        float v3 = p[(size_t)(i + 3) << 10];
        float n0 = fmaxf(mx[0], v0); sm[0] = sm[0] * __expf(mx[0] - n0) + __expf(v0 - n0); mx[0] = n0;
        float n1 = fmaxf(mx[1], v1); sm[1] = sm[1] * __expf(mx[1] - n1) + __expf(v1 - n1); mx[1] = n1;
        float n2 = fmaxf(mx[2], v2); sm[2] = sm[2] * __expf(mx[2] - n2) + __expf(v2 - n2); mx[2] = n2;
        float n3 = fmaxf(mx[3], v3); sm[3] = sm[3] * __expf(mx[3] - n3) + __expf(v3 - n3); mx[3] = n3;
    }
    float M = fmaxf(fmaxf(mx[0], mx[1]), fmaxf(mx[2], mx[3]));
    float Ssum = sm[0] * __expf(mx[0] - M) + sm[1] * __expf(mx[1] - M)
               + sm[2] * __expf(mx[2] - M) + sm[3] * __expf(mx[3] - M);
    g_cmax[b * NN + m] = M;
    g_csum[b * NN + m] = Ssum;
}

// =============================================================================
// Kernel 5: normalize in place. out[b,i,m] = exp(S - cmax[b,m]) / csum[b,m]
// =============================================================================
__global__ __launch_bounds__(256) void normalize_kernel(float* __restrict__ S)
{
    const int bi = blockIdx.x;                  // b*1024 + i
    const int b = bi >> 10;
    const int m = threadIdx.x * 4;
    size_t base = (size_t)bi * NN + m;

    float4 v  = *(const float4*)&S[base];
    float4 mx = *(const float4*)&g_cmax[b * NN + m];
    float4 sm = *(const float4*)&g_csum[b * NN + m];
    float4 o;
    o.x = __fdividef(__expf(v.x - mx.x), sm.x);
    o.y = __fdividef(__expf(v.y - mx.y), sm.y);
    o.z = __fdividef(__expf(v.z - mx.z), sm.z);
    o.w = __fdividef(__expf(v.w - mx.w), sm.w);
    *(float4*)&S[base] = o;
}

// =============================================================================
extern "C" void kernel_launch(void* const* d_in, const int* in_sizes, int n_in,
                              void* d_out, int out_size)
{
    (void)in_sizes; (void)n_in; (void)out_size;
    const float* x  = (const float*)d_in[0];
    const float* W1 = (const float*)d_in[1];
    const float* W2 = (const float*)d_in[2];
    const float* W3 = (const float*)d_in[3];
    const float* bs = (const float*)d_in[4];
    const float* Vs = (const float*)d_in[5];
    float* out = (float*)d_out;

    prep_kernel<<<BB * NN, 64>>>(x, W1, W2, W3);
    product_kernel<<<dim3(8, 8, BB), 256>>>(bs);
    gemm_kernel<<<dim3(8, 8, BB), 256>>>(Vs, out);
    colstats_kernel<<<BB * 16, 64>>>(out);
    normalize_kernel<<<BB * NN, 256>>>(out);
}

// round 6
// speedup vs baseline: 1.8880x; 1.8880x over previous
#include <cuda_runtime.h>
#include <cuda_bf16.h>
#include <cstdint>

#define BB 32
#define NN 1024
#define TT 64

typedef unsigned long long ull;

// ---------------- scratch (device globals) -----------------------------------
__device__ float         g_lhs[BB * NN * TT];             // 8 MB  (b,n,t)
__device__ float         g_rhs[BB * NN * TT];             // 8 MB  (b,m,t)
__device__ __nv_bfloat16 g_Vh[NN * NN];                   // 2 MB
__device__ __nv_bfloat16 g_Vl[NN * NN];                   // 2 MB
__device__ __nv_bfloat16 g_Gh[(size_t)BB * NN * NN];      // 64 MB (b,m,n) = P^T hi
__device__ __nv_bfloat16 g_Gl[(size_t)BB * NN * NN];      // 64 MB (b,m,n) = P^T lo
__device__ float         g_bsT[NN * NN];                  // 4 MB  bs transposed
__device__ float         g_cmax[BB * NN];
__device__ float         g_cinv[BB * NN];

// ---------------- f32x2 packed-FMA helpers ------------------------------------
__device__ __forceinline__ ull ffma2(ull a, ull b, ull c) {
    ull d;
    asm("fma.rn.f32x2 %0, %1, %2, %3;" : "=l"(d) : "l"(a), "l"(b), "l"(c));
    return d;
}
__device__ __forceinline__ ull pack2(float a) {
    ull d; asm("mov.b64 %0, {%1, %1};" : "=l"(d) : "f"(a)); return d;
}
__device__ __forceinline__ float2 unpack2(ull v) {
    float2 r; asm("mov.b64 {%0, %1}, %2;" : "=f"(r.x), "=f"(r.y) : "l"(v)); return r;
}

// ---------------- smem / cp.async / mma helpers (all sm_80+ legal) ------------
__device__ __forceinline__ uint32_t smem_u32(const void* p) {
    uint32_t a;
    asm("{ .reg .u64 t; cvta.to.shared.u64 t, %1; cvt.u32.u64 %0, t; }"
        : "=r"(a) : "l"(p));
    return a;
}
__device__ __forceinline__ void cp16(uint32_t dst, const void* src) {
    asm volatile("cp.async.cg.shared.global [%0], [%1], 16;" :: "r"(dst), "l"(src));
}
__device__ __forceinline__ void cp_commit() {
    asm volatile("cp.async.commit_group;" ::: "memory");
}
__device__ __forceinline__ void cp_wait3() {
    asm volatile("cp.async.wait_group 3;" ::: "memory");
}
#define LDSM_X4(r0, r1, r2, r3, addr)                                           \
    asm volatile("ldmatrix.sync.aligned.m8n8.x4.shared.b16 {%0,%1,%2,%3}, [%4];" \
        : "=r"(r0), "=r"(r1), "=r"(r2), "=r"(r3) : "r"(addr))

__device__ __forceinline__ void mma16816(float* d, const uint32_t* a,
                                         uint32_t b0, uint32_t b1) {
    asm volatile(
        "mma.sync.aligned.m16n8k16.row.col.f32.bf16.bf16.f32 "
        "{%0,%1,%2,%3}, {%4,%5,%6,%7}, {%8,%9}, {%0,%1,%2,%3};"
        : "+f"(d[0]), "+f"(d[1]), "+f"(d[2]), "+f"(d[3])
        : "r"(a[0]), "r"(a[1]), "r"(a[2]), "r"(a[3]), "r"(b0), "r"(b1));
}

// =============================================================================
// Kernel 1: prep — HBM-bound over 512 MB of x
// =============================================================================
__global__ __launch_bounds__(64) void prep_kernel(
    const float* __restrict__ x, const float* __restrict__ W1,
    const float* __restrict__ W2, const float* __restrict__ W3)
{
    __shared__ float sx[64][65];
    __shared__ float l1[64];
    __shared__ float sW1[64], sW3[64];

    const int t = threadIdx.x;
    sW1[t] = W1[t];
    sW3[t] = W3[t];

    const float4* x4 = reinterpret_cast<const float4*>(x) + (size_t)blockIdx.x * 1024;
#pragma unroll
    for (int i = 0; i < 16; i++) {
        int idx = i * 64 + t;
        float4 v = x4[idx];
        int f = idx >> 4;
        int c = (idx & 15) * 4;
        sx[f][c + 0] = v.x; sx[f][c + 1] = v.y;
        sx[f][c + 2] = v.z; sx[f][c + 3] = v.w;
    }
    __syncthreads();

    float acc = 0.f;
#pragma unroll
    for (int k = 0; k < 64; k++) acc += sx[t][k] * sW1[k];
    l1[t] = acc;

    float r = 0.f;
#pragma unroll
    for (int f = 0; f < 64; f++) r += sW3[f] * sx[f][t];

    __syncthreads();

    float l = 0.f;
#pragma unroll
    for (int f = 0; f < 64; f++) l += l1[f] * W2[f * 64 + t];

    size_t o = (size_t)blockIdx.x * 64 + t;
    g_lhs[o] = l;
    g_rhs[o] = r;
}

// =============================================================================
// Kernel 2a: split Vs into bf16 hi/lo
// =============================================================================
__global__ __launch_bounds__(256) void split_vs(const float* __restrict__ Vs)
{
    int i = (blockIdx.x * 256 + threadIdx.x) * 4;
    float4 v = *(const float4*)&Vs[i];
    __nv_bfloat16 h0 = __float2bfloat16(v.x), h1 = __float2bfloat16(v.y);
    __nv_bfloat16 h2 = __float2bfloat16(v.z), h3 = __float2bfloat16(v.w);
    __nv_bfloat16 l0 = __float2bfloat16(v.x - __bfloat162float(h0));
    __nv_bfloat16 l1 = __float2bfloat16(v.y - __bfloat162float(h1));
    __nv_bfloat16 l2 = __float2bfloat16(v.z - __bfloat162float(h2));
    __nv_bfloat16 l3 = __float2bfloat16(v.w - __bfloat162float(h3));
    __nv_bfloat162 ha; ha.x = h0; ha.y = h1;
    __nv_bfloat162 hb; hb.x = h2; hb.y = h3;
    __nv_bfloat162 la; la.x = l0; la.y = l1;
    __nv_bfloat162 lb; lb.x = l2; lb.y = l3;
    *(uint2*)&g_Vh[i] = make_uint2(*(uint32_t*)&ha, *(uint32_t*)&hb);
    *(uint2*)&g_Vl[i] = make_uint2(*(uint32_t*)&la, *(uint32_t*)&lb);
}

// =============================================================================
// Kernel 2b: transpose bias once: bsT[m][n] = bs[n][m]
// =============================================================================
__global__ __launch_bounds__(256) void transpose_bs(const float* __restrict__ bs)
{
    __shared__ float t[32][33];
    const int tx = threadIdx.x, ty = threadIdx.y;
    const int x0 = blockIdx.x * 32, y0 = blockIdx.y * 32;
#pragma unroll
    for (int r = 0; r < 4; r++)
        t[ty + r * 8][tx] = bs[(size_t)(y0 + ty + r * 8) * NN + x0 + tx];
    __syncthreads();
#pragma unroll
    for (int r = 0; r < 4; r++)
        g_bsT[(size_t)(x0 + ty + r * 8) * NN + y0 + tx] = t[tx][ty + r * 8];
}

// =============================================================================
// Kernel 3: product + sigmoid, transposed output, bf16 hi/lo split (FFMA2).
// Gt[b,m,n] = sigmoid( rhs[b,m,:]·lhs[b,n,:] + bsT[m,n] )
// =============================================================================
__global__ __launch_bounds__(256, 2) void product_t()
{
    __shared__ __align__(16) float Ls[16][132];
    __shared__ __align__(16) float Rs[16][132];

    const int tid = threadIdx.x;
    const int b  = blockIdx.z;
    const int m0 = blockIdx.y * 128;
    const int n0 = blockIdx.x * 128;

    const float* L = g_rhs + ((size_t)b * NN + m0) * TT;
    const float* R = g_lhs + ((size_t)b * NN + n0) * TT;

    const int i0 = (tid >> 4) * 8;
    const int j0 = (tid & 15) * 8;

    ull acc[8][4];
#pragma unroll
    for (int ii = 0; ii < 8; ii++)
#pragma unroll
        for (int jj = 0; jj < 4; jj++) acc[ii][jj] = 0ull;

#pragma unroll 1
    for (int kt = 0; kt < 4; kt++) {
        const int k0 = kt * 16;
        __syncthreads();
#pragma unroll
        for (int rr = 0; rr < 2; rr++) {
            int g = tid + 256 * rr;
            int row = g >> 2;
            int c = (g & 3) * 4;
            float4 va = *(const float4*)(L + (size_t)row * TT + k0 + c);
            float4 vb = *(const float4*)(R + (size_t)row * TT + k0 + c);
            Ls[c + 0][row] = va.x; Ls[c + 1][row] = va.y;
            Ls[c + 2][row] = va.z; Ls[c + 3][row] = va.w;
            Rs[c + 0][row] = vb.x; Rs[c + 1][row] = vb.y;
            Rs[c + 2][row] = vb.z; Rs[c + 3][row] = vb.w;
        }
        __syncthreads();
#pragma unroll
        for (int k = 0; k < 16; k++) {
            float a[8];
            ull bv[4];
#pragma unroll
            for (int ii = 0; ii < 8; ii++) a[ii] = Ls[k][i0 + ii];
#pragma unroll
            for (int jj = 0; jj < 4; jj++)
                bv[jj] = *(const ull*)&Rs[k][j0 + jj * 2];
#pragma unroll
            for (int ii = 0; ii < 8; ii++) {
                ull ap = pack2(a[ii]);
#pragma unroll
                for (int jj = 0; jj < 4; jj++)
                    acc[ii][jj] = ffma2(ap, bv[jj], acc[ii][jj]);
            }
        }
    }

#pragma unroll
    for (int ii = 0; ii < 8; ii++) {
        int m = m0 + i0 + ii;
        uint32_t hw[4], lw[4];
#pragma unroll
        for (int jj = 0; jj < 4; jj++) {
            float2 p = unpack2(acc[ii][jj]);
            float2 bb = *(const float2*)&g_bsT[(size_t)m * NN + n0 + j0 + jj * 2];
            float gx = 1.f / (1.f + __expf(-(p.x + bb.x)));
            float gy = 1.f / (1.f + __expf(-(p.y + bb.y)));
            __nv_bfloat16 hx = __float2bfloat16(gx);
            __nv_bfloat16 hy = __float2bfloat16(gy);
            __nv_bfloat162 hh; hh.x = hx; hh.y = hy;
            __nv_bfloat162 ll;
            ll.x = __float2bfloat16(gx - __bfloat162float(hx));
            ll.y = __float2bfloat16(gy - __bfloat162float(hy));
            hw[jj] = *(uint32_t*)&hh;
            lw[jj] = *(uint32_t*)&ll;
        }
        size_t o = ((size_t)b << 20) + ((size_t)m << 10) + n0 + j0;
        *(uint4*)&g_Gh[o] = make_uint4(hw[0], hw[1], hw[2], hw[3]);
        *(uint4*)&g_Gl[o] = make_uint4(lw[0], lw[1], lw[2], lw[3]);
    }
}

// =============================================================================
// Kernel 4: tensor-core GEMM via mma.sync (legal at base sm_100).
// S[b,i,m] = sum_n Vs[i,n] * Gt[b,m,n]   (both operands K-major -> row.col mma)
// Split precision: D = Vh*Gh + Vh*Gl + Vl*Gh  -> 48 kTiles of 64.
// 128x128 CTA tile, 8 warps (32x64 each), 4-stage cp.async pipeline,
// XOR-swizzled smem, ldmatrix.x4 fragments, fp32 accumulators.
// =============================================================================
#define G_STAGES 4
#define G_STAGE_BYTES 32768   // A 128x64 bf16 (16KB) + B 128x64 bf16 (16KB)
#define G_SMEM_BYTES (G_STAGES * G_STAGE_BYTES)   // 128 KB

__global__ void __launch_bounds__(256, 1) gemm_mma(float* __restrict__ S)
{
    extern __shared__ __align__(1024) char dsm[];
    const uint32_t sm0 = smem_u32(dsm);

    const int tid  = threadIdx.x;
    const int lane = tid & 31;
    const int w    = tid >> 5;
    const int b    = blockIdx.z;
    const int i0g  = blockIdx.y * 128;
    const int m0   = blockIdx.x * 128;

    const int wi0 = (w >> 1) * 32;   // warp row offset (i), 0/32/64/96
    const int wm0 = (w & 1) * 64;    // warp col offset (m), 0/64

    // per-thread loader decomposition: 4 A-chunks + 4 B-chunks of 16B per stage
    const int ld_row = tid >> 3;     // 0..31  (+32 per iteration)
    const int ld_c   = tid & 7;      // 16B chunk within 128B row

    // ldmatrix per-thread bases
    const int a_row  = wi0 + (lane & 15);       // (row&7) == lane&7
    const int a_half = lane >> 4;               // k half (0/1)
    const int b_nB   = (lane & 7) + ((lane >> 4) << 3);
    const int b_half = (lane >> 3) & 1;
    const int swz    = lane & 7;                // XOR term for both A and B

    float acc[2][8][4];
#pragma unroll
    for (int mt = 0; mt < 2; mt++)
#pragma unroll
        for (int j = 0; j < 8; j++)
#pragma unroll
            for (int q = 0; q < 4; q++) acc[mt][j][q] = 0.f;

    auto load_stage = [&](int kk) {
        const int pass = kk >> 4;
        const int k0   = (kk & 15) * 64;
        const __nv_bfloat16* As = (pass < 2) ? g_Vh : g_Vl;
        const __nv_bfloat16* Bs = (pass == 1) ? g_Gl : g_Gh;
        const uint32_t sb = sm0 + (kk & 3) * G_STAGE_BYTES;
#pragma unroll
        for (int it = 0; it < 4; it++) {
            int row = ld_row + it * 32;
            uint32_t soff = row * 128 + ((ld_c ^ (row & 7)) * 16);
            cp16(sb + soff,
                 As + (((size_t)(i0g + row)) << 10) + k0 + ld_c * 8);
            cp16(sb + 16384 + soff,
                 Bs + ((size_t)b << 20) + (((size_t)(m0 + row)) << 10) + k0 + ld_c * 8);
        }
        cp_commit();
    };

    load_stage(0);
    load_stage(1);
    load_stage(2);

#pragma unroll 1
    for (int kk = 0; kk < 48; kk++) {
        if (kk + 3 < 48) load_stage(kk + 3);
        else cp_commit();                       // keep wait_group invariant exact
        cp_wait3();
        __syncthreads();

        const uint32_t sb = sm0 + (kk & 3) * G_STAGE_BYTES;
        const uint32_t Ab = sb;
        const uint32_t Bb = sb + 16384;

#pragma unroll
        for (int ks = 0; ks < 4; ks++) {
            // A fragments: 2 m16 tiles
            uint32_t a[2][4];
#pragma unroll
            for (int mt = 0; mt < 2; mt++) {
                uint32_t addr = Ab + (a_row + mt * 16) * 128
                              + (((2 * ks + a_half) ^ swz) * 16);
                LDSM_X4(a[mt][0], a[mt][1], a[mt][2], a[mt][3], addr);
            }
            // B fragments: 4 n16 groups covering 64 m-cols
            uint32_t bf[4][4];
#pragma unroll
            for (int nt = 0; nt < 4; nt++) {
                uint32_t addr = Bb + (wm0 + nt * 16 + b_nB) * 128
                              + (((2 * ks + b_half) ^ swz) * 16);
                LDSM_X4(bf[nt][0], bf[nt][1], bf[nt][2], bf[nt][3], addr);
            }
#pragma unroll
            for (int mt = 0; mt < 2; mt++)
#pragma unroll
                for (int nt = 0; nt < 4; nt++) {
                    mma16816(acc[mt][nt * 2 + 0], a[mt], bf[nt][0], bf[nt][1]);
                    mma16816(acc[mt][nt * 2 + 1], a[mt], bf[nt][2], bf[nt][3]);
                }
        }
        __syncthreads();
    }

    // epilogue: write 32x64 fp32 per warp
    float* Sb = S + ((size_t)b << 20);
#pragma unroll
    for (int mt = 0; mt < 2; mt++) {
        int r0 = i0g + wi0 + mt * 16 + (lane >> 2);
#pragma unroll
        for (int nt = 0; nt < 4; nt++)
#pragma unroll
            for (int h = 0; h < 2; h++) {
                int j = nt * 2 + h;
                int cm = m0 + wm0 + nt * 16 + h * 8 + (lane & 3) * 2;
                float2 v0 = make_float2(acc[mt][j][0], acc[mt][j][1]);
                float2 v1 = make_float2(acc[mt][j][2], acc[mt][j][3]);
                *(float2*)&Sb[((size_t)r0 << 10) + cm] = v0;
                *(float2*)&Sb[((size_t)(r0 + 8) << 10) + cm] = v1;
            }
    }
}

// =============================================================================
// Kernel 5: column softmax stats (axis=1). 4 threads per column + smem combine.
// =============================================================================
__global__ __launch_bounds__(256) void colstats_kernel(const float* __restrict__ S)
{
    __shared__ float smx[4][64], ssm[4][64];
    const int b  = blockIdx.x >> 4;
    const int m0 = (blockIdx.x & 15) << 6;
    const int ml = threadIdx.x & 63;
    const int seg = threadIdx.x >> 6;
    const float* p = S + ((size_t)b << 20) + (((size_t)seg * 256) << 10) + m0 + ml;

    float mx[4] = {-1e30f, -1e30f, -1e30f, -1e30f};
    float sm[4] = {0.f, 0.f, 0.f, 0.f};
#pragma unroll 2
    for (int i = 0; i < 256; i += 4) {
        float v0 = p[(size_t)(i + 0) << 10];
        float v1 = p[(size_t)(i + 1) << 10];
        float v2 = p[(size_t)(i + 2) << 10];
        float v3 = p[(size_t)(i + 3) << 10];
        float n0 = fmaxf(mx[0], v0); sm[0] = sm[0] * __expf(mx[0] - n0) + __expf(v0 - n0); mx[0] = n0;
        float n1 = fmaxf(mx[1], v1); sm[1] = sm[1] * __expf(mx[1] - n1) + __expf(v1 - n1); mx[1] = n1;
        float n2 = fmaxf(mx[2], v2); sm[2] = sm[2] * __expf(mx[2] - n2) + __expf(v2 - n2); mx[2] = n2;
        float n3 = fmaxf(mx[3], v3); sm[3] = sm[3] * __expf(mx[3] - n3) + __expf(v3 - n3); mx[3] = n3;
    }
    float M = fmaxf(fmaxf(mx[0], mx[1]), fmaxf(mx[2], mx[3]));
    float Ss = sm[0] * __expf(mx[0] - M) + sm[1] * __expf(mx[1] - M)
             + sm[2] * __expf(mx[2] - M) + sm[3] * __expf(mx[3] - M);
    smx[seg][ml] = M;
    ssm[seg][ml] = Ss;
    __syncthreads();
    if (seg == 0) {
        float Mt = smx[0][ml], St = ssm[0][ml];
#pragma unroll
        for (int s = 1; s < 4; s++) {
            float M2 = smx[s][ml];
            float nm = fmaxf(Mt, M2);
            St = St * __expf(Mt - nm) + ssm[s][ml] * __expf(M2 - nm);
            Mt = nm;
        }
        g_cmax[b * NN + m0 + ml] = Mt;
        g_cinv[b * NN + m0 + ml] = __fdividef(1.f, St);
    }
}

// =============================================================================
// Kernel 6: normalize in place
// =============================================================================
__global__ __launch_bounds__(256) void normalize_kernel(float* __restrict__ S)
{
    const int bi = blockIdx.x;
    const int b = bi >> 10;
    const int m = threadIdx.x * 4;
    size_t base = (size_t)bi * NN + m;

    float4 v  = *(const float4*)&S[base];
    float4 mx = *(const float4*)&g_cmax[b * NN + m];
    float4 iv = *(const float4*)&g_cinv[b * NN + m];
    float4 o;
    o.x = __expf(v.x - mx.x) * iv.x;
    o.y = __expf(v.y - mx.y) * iv.y;
    o.z = __expf(v.z - mx.z) * iv.z;
    o.w = __expf(v.w - mx.w) * iv.w;
    *(float4*)&S[base] = o;
}

// =============================================================================
extern "C" void kernel_launch(void* const* d_in, const int* in_sizes, int n_in,
                              void* d_out, int out_size)
{
    (void)in_sizes; (void)n_in; (void)out_size;
    const float* x  = (const float*)d_in[0];
    const float* W1 = (const float*)d_in[1];
    const float* W2 = (const float*)d_in[2];
    const float* W3 = (const float*)d_in[3];
    const float* bs = (const float*)d_in[4];
    const float* Vs = (const float*)d_in[5];
    float* out = (float*)d_out;

    cudaFuncSetAttribute(gemm_mma, cudaFuncAttributeMaxDynamicSharedMemorySize,
                         G_SMEM_BYTES);

    prep_kernel<<<BB * NN, 64>>>(x, W1, W2, W3);
    split_vs<<<NN * NN / 1024, 256>>>(Vs);
    transpose_bs<<<dim3(32, 32), dim3(32, 8)>>>(bs);
    product_t<<<dim3(8, 8, BB), 256>>>();
    gemm_mma<<<dim3(8, 8, BB), 256, G_SMEM_BYTES>>>(out);
    colstats_kernel<<<512, 256>>>(out);
    normalize_kernel<<<BB * NN, 256>>>(out);
}

// round 7
// speedup vs baseline: 2.1380x; 1.1324x over previous
#include <cuda_runtime.h>
#include <cuda_bf16.h>
#include <cstdint>

#define BB 32
#define NN 1024
#define TT 64

typedef unsigned long long ull;

// ---------------- scratch (device globals) -----------------------------------
__device__ float         g_lhs[BB * NN * TT];             // 8 MB  (b,n,t)
__device__ float         g_rhs[BB * NN * TT];             // 8 MB  (b,m,t)
__device__ __nv_bfloat16 g_Vh[NN * NN];                   // 2 MB
__device__ __nv_bfloat16 g_Vl[NN * NN];                   // 2 MB
__device__ __nv_bfloat16 g_Gh[(size_t)BB * NN * NN];      // 64 MB (b,m,n) = P^T hi
__device__ __nv_bfloat16 g_Gl[(size_t)BB * NN * NN];      // 64 MB (b,m,n) = P^T lo
__device__ float         g_bsT[NN * NN];                  // 4 MB  bs transposed
__device__ float         g_cinv[BB * NN];                 // per-(b,m) 1/colsum

// ---------------- f32x2 packed-FMA helpers ------------------------------------
__device__ __forceinline__ ull ffma2(ull a, ull b, ull c) {
    ull d;
    asm("fma.rn.f32x2 %0, %1, %2, %3;" : "=l"(d) : "l"(a), "l"(b), "l"(c));
    return d;
}
__device__ __forceinline__ ull pack2(float a) {
    ull d; asm("mov.b64 %0, {%1, %1};" : "=l"(d) : "f"(a)); return d;
}
__device__ __forceinline__ float2 unpack2(ull v) {
    float2 r; asm("mov.b64 {%0, %1}, %2;" : "=f"(r.x), "=f"(r.y) : "l"(v)); return r;
}

// ---------------- smem / cp.async / mma helpers (all sm_80+ legal) ------------
__device__ __forceinline__ uint32_t smem_u32(const void* p) {
    uint32_t a;
    asm("{ .reg .u64 t; cvta.to.shared.u64 t, %1; cvt.u32.u64 %0, t; }"
        : "=r"(a) : "l"(p));
    return a;
}
__device__ __forceinline__ void cp16(uint32_t dst, const void* src) {
    asm volatile("cp.async.cg.shared.global [%0], [%1], 16;" :: "r"(dst), "l"(src));
}
__device__ __forceinline__ void cp_commit() {
    asm volatile("cp.async.commit_group;" ::: "memory");
}
__device__ __forceinline__ void cp_wait2() {
    asm volatile("cp.async.wait_group 2;" ::: "memory");
}
#define LDSM_X4(r0, r1, r2, r3, addr)                                           \
    asm volatile("ldmatrix.sync.aligned.m8n8.x4.shared.b16 {%0,%1,%2,%3}, [%4];" \
        : "=r"(r0), "=r"(r1), "=r"(r2), "=r"(r3) : "r"(addr))

__device__ __forceinline__ void mma16816(float* d, const uint32_t* a,
                                         uint32_t b0, uint32_t b1) {
    asm volatile(
        "mma.sync.aligned.m16n8k16.row.col.f32.bf16.bf16.f32 "
        "{%0,%1,%2,%3}, {%4,%5,%6,%7}, {%8,%9}, {%0,%1,%2,%3};"
        : "+f"(d[0]), "+f"(d[1]), "+f"(d[2]), "+f"(d[3])
        : "r"(a[0]), "r"(a[1]), "r"(a[2]), "r"(a[3]), "r"(b0), "r"(b1));
}

// =============================================================================
// Kernel 1: prep — HBM-bound over 512 MB of x
// =============================================================================
__global__ __launch_bounds__(64) void prep_kernel(
    const float* __restrict__ x, const float* __restrict__ W1,
    const float* __restrict__ W2, const float* __restrict__ W3)
{
    __shared__ float sx[64][65];
    __shared__ float l1[64];
    __shared__ float sW1[64], sW3[64];

    const int t = threadIdx.x;
    sW1[t] = W1[t];
    sW3[t] = W3[t];

    const float4* x4 = reinterpret_cast<const float4*>(x) + (size_t)blockIdx.x * 1024;
#pragma unroll
    for (int i = 0; i < 16; i++) {
        int idx = i * 64 + t;
        float4 v = x4[idx];
        int f = idx >> 4;
        int c = (idx & 15) * 4;
        sx[f][c + 0] = v.x; sx[f][c + 1] = v.y;
        sx[f][c + 2] = v.z; sx[f][c + 3] = v.w;
    }
    __syncthreads();

    float acc = 0.f;
#pragma unroll
    for (int k = 0; k < 64; k++) acc += sx[t][k] * sW1[k];
    l1[t] = acc;

    float r = 0.f;
#pragma unroll
    for (int f = 0; f < 64; f++) r += sW3[f] * sx[f][t];

    __syncthreads();

    float l = 0.f;
#pragma unroll
    for (int f = 0; f < 64; f++) l += l1[f] * W2[f * 64 + t];

    size_t o = (size_t)blockIdx.x * 64 + t;
    g_lhs[o] = l;
    g_rhs[o] = r;
}

// =============================================================================
// Kernel 2a: split Vs into bf16 hi/lo
// =============================================================================
__global__ __launch_bounds__(256) void split_vs(const float* __restrict__ Vs)
{
    int i = (blockIdx.x * 256 + threadIdx.x) * 4;
    float4 v = *(const float4*)&Vs[i];
    __nv_bfloat16 h0 = __float2bfloat16(v.x), h1 = __float2bfloat16(v.y);
    __nv_bfloat16 h2 = __float2bfloat16(v.z), h3 = __float2bfloat16(v.w);
    __nv_bfloat16 l0 = __float2bfloat16(v.x - __bfloat162float(h0));
    __nv_bfloat16 l1 = __float2bfloat16(v.y - __bfloat162float(h1));
    __nv_bfloat16 l2 = __float2bfloat16(v.z - __bfloat162float(h2));
    __nv_bfloat16 l3 = __float2bfloat16(v.w - __bfloat162float(h3));
    __nv_bfloat162 ha; ha.x = h0; ha.y = h1;
    __nv_bfloat162 hb; hb.x = h2; hb.y = h3;
    __nv_bfloat162 la; la.x = l0; la.y = l1;
    __nv_bfloat162 lb; lb.x = l2; lb.y = l3;
    *(uint2*)&g_Vh[i] = make_uint2(*(uint32_t*)&ha, *(uint32_t*)&hb);
    *(uint2*)&g_Vl[i] = make_uint2(*(uint32_t*)&la, *(uint32_t*)&lb);
}

// =============================================================================
// Kernel 2b: transpose bias once: bsT[m][n] = bs[n][m]
// =============================================================================
__global__ __launch_bounds__(256) void transpose_bs(const float* __restrict__ bs)
{
    __shared__ float t[32][33];
    const int tx = threadIdx.x, ty = threadIdx.y;
    const int x0 = blockIdx.x * 32, y0 = blockIdx.y * 32;
#pragma unroll
    for (int r = 0; r < 4; r++)
        t[ty + r * 8][tx] = bs[(size_t)(y0 + ty + r * 8) * NN + x0 + tx];
    __syncthreads();
#pragma unroll
    for (int r = 0; r < 4; r++)
        g_bsT[(size_t)(x0 + ty + r * 8) * NN + y0 + tx] = t[tx][ty + r * 8];
}

// =============================================================================
// Kernel 3: product + sigmoid, transposed output, bf16 hi/lo split (FFMA2).
// Gt[b,m,n] = sigmoid( rhs[b,m,:]·lhs[b,n,:] + bsT[m,n] )
// =============================================================================
__global__ __launch_bounds__(256, 2) void product_t()
{
    __shared__ __align__(16) float Ls[16][132];
    __shared__ __align__(16) float Rs[16][132];

    const int tid = threadIdx.x;
    const int b  = blockIdx.z;
    const int m0 = blockIdx.y * 128;
    const int n0 = blockIdx.x * 128;

    const float* L = g_rhs + ((size_t)b * NN + m0) * TT;
    const float* R = g_lhs + ((size_t)b * NN + n0) * TT;

    const int i0 = (tid >> 4) * 8;
    const int j0 = (tid & 15) * 8;

    ull acc[8][4];
#pragma unroll
    for (int ii = 0; ii < 8; ii++)
#pragma unroll
        for (int jj = 0; jj < 4; jj++) acc[ii][jj] = 0ull;

#pragma unroll 1
    for (int kt = 0; kt < 4; kt++) {
        const int k0 = kt * 16;
        __syncthreads();
#pragma unroll
        for (int rr = 0; rr < 2; rr++) {
            int g = tid + 256 * rr;
            int row = g >> 2;
            int c = (g & 3) * 4;
            float4 va = *(const float4*)(L + (size_t)row * TT + k0 + c);
            float4 vb = *(const float4*)(R + (size_t)row * TT + k0 + c);
            Ls[c + 0][row] = va.x; Ls[c + 1][row] = va.y;
            Ls[c + 2][row] = va.z; Ls[c + 3][row] = va.w;
            Rs[c + 0][row] = vb.x; Rs[c + 1][row] = vb.y;
            Rs[c + 2][row] = vb.z; Rs[c + 3][row] = vb.w;
        }
        __syncthreads();
#pragma unroll
        for (int k = 0; k < 16; k++) {
            float a[8];
            ull bv[4];
#pragma unroll
            for (int ii = 0; ii < 8; ii++) a[ii] = Ls[k][i0 + ii];
#pragma unroll
            for (int jj = 0; jj < 4; jj++)
                bv[jj] = *(const ull*)&Rs[k][j0 + jj * 2];
#pragma unroll
            for (int ii = 0; ii < 8; ii++) {
                ull ap = pack2(a[ii]);
#pragma unroll
                for (int jj = 0; jj < 4; jj++)
                    acc[ii][jj] = ffma2(ap, bv[jj], acc[ii][jj]);
            }
        }
    }

#pragma unroll
    for (int ii = 0; ii < 8; ii++) {
        int m = m0 + i0 + ii;
        uint32_t hw[4], lw[4];
#pragma unroll
        for (int jj = 0; jj < 4; jj++) {
            float2 p = unpack2(acc[ii][jj]);
            float2 bb = *(const float2*)&g_bsT[(size_t)m * NN + n0 + j0 + jj * 2];
            float gx = 1.f / (1.f + __expf(-(p.x + bb.x)));
            float gy = 1.f / (1.f + __expf(-(p.y + bb.y)));
            __nv_bfloat16 hx = __float2bfloat16(gx);
            __nv_bfloat16 hy = __float2bfloat16(gy);
            __nv_bfloat162 hh; hh.x = hx; hh.y = hy;
            __nv_bfloat162 ll;
            ll.x = __float2bfloat16(gx - __bfloat162float(hx));
            ll.y = __float2bfloat16(gy - __bfloat162float(hy));
            hw[jj] = *(uint32_t*)&hh;
            lw[jj] = *(uint32_t*)&ll;
        }
        size_t o = ((size_t)b << 20) + ((size_t)m << 10) + n0 + j0;
        *(uint4*)&g_Gh[o] = make_uint4(hw[0], hw[1], hw[2], hw[3]);
        *(uint4*)&g_Gl[o] = make_uint4(lw[0], lw[1], lw[2], lw[3]);
    }
}

// =============================================================================
// Kernel 4: fused 3-pass tensor-core GEMM via mma.sync.
// S[b,i,m] = sum_n Vs[i,n] * Gt[b,m,n];   D = Vh·Gh + Vh·Gl + Vl·Gh
// Per 64-k stage load {Vh, Vl, Gh, Gl} tiles ONCE (64 KB) and issue all three
// products from shared fragments. 3-stage cp.async ring (192 KB), 16 stages.
// Epilogue writes exp(S) (softmax-no-max; logits bounded, fp32-safe).
// =============================================================================
#define GF_STAGES 3
#define GF_STAGE_BYTES 65536
#define GF_SMEM (GF_STAGES * GF_STAGE_BYTES)   // 192 KB

__global__ void __launch_bounds__(256, 1) gemm_fused(float* __restrict__ S)
{
    extern __shared__ __align__(1024) char dsm[];
    const uint32_t sm0 = smem_u32(dsm);

    const int tid  = threadIdx.x;
    const int lane = tid & 31;
    const int w    = tid >> 5;
    const int b    = blockIdx.z;
    const int i0g  = blockIdx.y * 128;
    const int m0   = blockIdx.x * 128;

    const int wi0 = (w >> 1) * 32;   // warp row offset (i)
    const int wm0 = (w & 1) * 64;    // warp col offset (m)

    const int ld_row = tid >> 3;     // 0..31 (+32 per it)
    const int ld_c   = tid & 7;

    const int a_row  = wi0 + (lane & 15);
    const int a_half = lane >> 4;
    const int b_nB   = (lane & 7) + ((lane >> 4) << 3);
    const int b_half = (lane >> 3) & 1;
    const int swz    = lane & 7;

    float acc[2][8][4];
#pragma unroll
    for (int mt = 0; mt < 2; mt++)
#pragma unroll
        for (int j = 0; j < 8; j++)
#pragma unroll
            for (int q = 0; q < 4; q++) acc[mt][j][q] = 0.f;

    auto load_stage = [&](int kk) {
        const int k0 = kk * 64;
        const uint32_t sb = sm0 + (kk % GF_STAGES) * GF_STAGE_BYTES;
#pragma unroll
        for (int it = 0; it < 4; it++) {
            int row = ld_row + it * 32;
            uint32_t soff = row * 128 + ((ld_c ^ (row & 7)) * 16);
            size_t aoff = (((size_t)(i0g + row)) << 10) + k0 + ld_c * 8;
            size_t boff = ((size_t)b << 20) + (((size_t)(m0 + row)) << 10) + k0 + ld_c * 8;
            cp16(sb + soff,         g_Vh + aoff);
            cp16(sb + 16384 + soff, g_Vl + aoff);
            cp16(sb + 32768 + soff, g_Gh + boff);
            cp16(sb + 49152 + soff, g_Gl + boff);
        }
        cp_commit();
    };

    load_stage(0);
    load_stage(1);

#pragma unroll 1
    for (int kk = 0; kk < 16; kk++) {
        if (kk + 2 < 16) load_stage(kk + 2);
        else cp_commit();                 // keep wait_group invariant exact
        cp_wait2();
        __syncthreads();

        const uint32_t sb = sm0 + (kk % GF_STAGES) * GF_STAGE_BYTES;

#pragma unroll
        for (int ks = 0; ks < 4; ks++) {
            uint32_t ah[2][4], al[2][4];
#pragma unroll
            for (int mt = 0; mt < 2; mt++) {
                uint32_t off = (a_row + mt * 16) * 128
                             + (((2 * ks + a_half) ^ swz) * 16);
                LDSM_X4(ah[mt][0], ah[mt][1], ah[mt][2], ah[mt][3], sb + off);
                LDSM_X4(al[mt][0], al[mt][1], al[mt][2], al[mt][3], sb + 16384 + off);
            }
            uint32_t bh[4][4], bl[4][4];
#pragma unroll
            for (int nt = 0; nt < 4; nt++) {
                uint32_t off = (wm0 + nt * 16 + b_nB) * 128
                             + (((2 * ks + b_half) ^ swz) * 16);
                LDSM_X4(bh[nt][0], bh[nt][1], bh[nt][2], bh[nt][3], sb + 32768 + off);
                LDSM_X4(bl[nt][0], bl[nt][1], bl[nt][2], bl[nt][3], sb + 49152 + off);
            }
#pragma unroll
            for (int mt = 0; mt < 2; mt++)
#pragma unroll
                for (int nt = 0; nt < 4; nt++) {
                    mma16816(acc[mt][nt * 2 + 0], ah[mt], bh[nt][0], bh[nt][1]);
                    mma16816(acc[mt][nt * 2 + 1], ah[mt], bh[nt][2], bh[nt][3]);
                    mma16816(acc[mt][nt * 2 + 0], ah[mt], bl[nt][0], bl[nt][1]);
                    mma16816(acc[mt][nt * 2 + 1], ah[mt], bl[nt][2], bl[nt][3]);
                    mma16816(acc[mt][nt * 2 + 0], al[mt], bh[nt][0], bh[nt][1]);
                    mma16816(acc[mt][nt * 2 + 1], al[mt], bh[nt][2], bh[nt][3]);
                }
        }
        __syncthreads();
    }

    // epilogue: write exp(S) (32x64 fp32 per warp)
    float* Sb = S + ((size_t)b << 20);
#pragma unroll
    for (int mt = 0; mt < 2; mt++) {
        int r0 = i0g + wi0 + mt * 16 + (lane >> 2);
#pragma unroll
        for (int nt = 0; nt < 4; nt++)
#pragma unroll
            for (int h = 0; h < 2; h++) {
                int j = nt * 2 + h;
                int cm = m0 + wm0 + nt * 16 + h * 8 + (lane & 3) * 2;
                float2 v0 = make_float2(__expf(acc[mt][j][0]), __expf(acc[mt][j][1]));
                float2 v1 = make_float2(__expf(acc[mt][j][2]), __expf(acc[mt][j][3]));
                *(float2*)&Sb[((size_t)r0 << 10) + cm] = v0;
                *(float2*)&Sb[((size_t)(r0 + 8) << 10) + cm] = v1;
            }
    }
}

// =============================================================================
// Kernel 5: column sums of exp(S) (axis=1). 4 threads per column, smem combine.
// =============================================================================
__global__ __launch_bounds__(256) void colsum_kernel(const float* __restrict__ S)
{
    __shared__ float ssm[4][64];
    const int b   = blockIdx.x >> 4;
    const int m0  = (blockIdx.x & 15) << 6;
    const int ml  = threadIdx.x & 63;
    const int seg = threadIdx.x >> 6;
    const float* p = S + ((size_t)b << 20) + (((size_t)seg * 256) << 10) + m0 + ml;

    float s0 = 0.f, s1 = 0.f, s2 = 0.f, s3 = 0.f;
#pragma unroll 4
    for (int i = 0; i < 256; i += 4) {
        s0 += p[(size_t)(i + 0) << 10];
        s1 += p[(size_t)(i + 1) << 10];
        s2 += p[(size_t)(i + 2) << 10];
        s3 += p[(size_t)(i + 3) << 10];
    }
    ssm[seg][ml] = (s0 + s1) + (s2 + s3);
    __syncthreads();
    if (seg == 0) {
        float t = (ssm[0][ml] + ssm[1][ml]) + (ssm[2][ml] + ssm[3][ml]);
        g_cinv[b * NN + m0 + ml] = __fdividef(1.f, t);
    }
}

// =============================================================================
// Kernel 6: normalize in place: out = expS * (1/colsum)
// =============================================================================
__global__ __launch_bounds__(256) void normalize_kernel(float* __restrict__ S)
{
    const int bi = blockIdx.x;
    const int b = bi >> 10;
    const int m = threadIdx.x * 4;
    size_t base = (size_t)bi * NN + m;

    float4 v  = *(const float4*)&S[base];
    float4 iv = *(const float4*)&g_cinv[b * NN + m];
    float4 o;
    o.x = v.x * iv.x;
    o.y = v.y * iv.y;
    o.z = v.z * iv.z;
    o.w = v.w * iv.w;
    *(float4*)&S[base] = o;
}

// =============================================================================
extern "C" void kernel_launch(void* const* d_in, const int* in_sizes, int n_in,
                              void* d_out, int out_size)
{
    (void)in_sizes; (void)n_in; (void)out_size;
    const float* x  = (const float*)d_in[0];
    const float* W1 = (const float*)d_in[1];
    const float* W2 = (const float*)d_in[2];
    const float* W3 = (const float*)d_in[3];
    const float* bs = (const float*)d_in[4];
    const float* Vs = (const float*)d_in[5];
    float* out = (float*)d_out;

    cudaFuncSetAttribute(gemm_fused, cudaFuncAttributeMaxDynamicSharedMemorySize,
                         GF_SMEM);

    prep_kernel<<<BB * NN, 64>>>(x, W1, W2, W3);
    split_vs<<<NN * NN / 1024, 256>>>(Vs);
    transpose_bs<<<dim3(32, 32), dim3(32, 8)>>>(bs);
    product_t<<<dim3(8, 8, BB), 256>>>();
    gemm_fused<<<dim3(8, 8, BB), 256, GF_SMEM>>>(out);
    colsum_kernel<<<512, 256>>>(out);
    normalize_kernel<<<BB * NN, 256>>>(out);
}

// round 8
// speedup vs baseline: 2.2798x; 1.0663x over previous
#include <cuda_runtime.h>
#include <cuda_bf16.h>
#include <cstdint>

#define BB 32
#define NN 1024
#define TT 64

typedef unsigned long long ull;

// ---------------- scratch (device globals) -----------------------------------
__device__ __nv_bfloat16 g_lh_h[BB * NN * TT];            // 4 MB  lhs hi (b,n,t)
__device__ __nv_bfloat16 g_lh_l[BB * NN * TT];            // 4 MB  lhs lo
__device__ __nv_bfloat16 g_rh_h[BB * NN * TT];            // 4 MB  rhs hi (b,m,t)
__device__ __nv_bfloat16 g_rh_l[BB * NN * TT];            // 4 MB  rhs lo
__device__ __nv_bfloat16 g_Vh[NN * NN];                   // 2 MB
__device__ __nv_bfloat16 g_Vl[NN * NN];                   // 2 MB
__device__ __nv_bfloat16 g_Gh[(size_t)BB * NN * NN];      // 64 MB (b,m,n) = P^T hi
__device__ __nv_bfloat16 g_Gl[(size_t)BB * NN * NN];      // 64 MB (b,m,n) = P^T lo
__device__ float         g_bsT[NN * NN];                  // 4 MB  bs transposed
__device__ float         g_part[8][BB * NN];              // 1 MB  per-i-tile col partials
__device__ float         g_cinv[BB * NN];                 // per-(b,m) 1/colsum

// ---------------- smem / cp.async / mma helpers (all sm_80+ legal) ------------
__device__ __forceinline__ uint32_t smem_u32(const void* p) {
    uint32_t a;
    asm("{ .reg .u64 t; cvta.to.shared.u64 t, %1; cvt.u32.u64 %0, t; }"
        : "=r"(a) : "l"(p));
    return a;
}
__device__ __forceinline__ void cp16(uint32_t dst, const void* src) {
    asm volatile("cp.async.cg.shared.global [%0], [%1], 16;" :: "r"(dst), "l"(src));
}
__device__ __forceinline__ void cp_commit() {
    asm volatile("cp.async.commit_group;" ::: "memory");
}
__device__ __forceinline__ void cp_wait2() {
    asm volatile("cp.async.wait_group 2;" ::: "memory");
}
__device__ __forceinline__ void cp_wait0() {
    asm volatile("cp.async.wait_group 0;" ::: "memory");
}
#define LDSM_X4(r0, r1, r2, r3, addr)                                           \
    asm volatile("ldmatrix.sync.aligned.m8n8.x4.shared.b16 {%0,%1,%2,%3}, [%4];" \
        : "=r"(r0), "=r"(r1), "=r"(r2), "=r"(r3) : "r"(addr))

__device__ __forceinline__ void mma16816(float* d, const uint32_t* a,
                                         uint32_t b0, uint32_t b1) {
    asm volatile(
        "mma.sync.aligned.m16n8k16.row.col.f32.bf16.bf16.f32 "
        "{%0,%1,%2,%3}, {%4,%5,%6,%7}, {%8,%9}, {%0,%1,%2,%3};"
        : "+f"(d[0]), "+f"(d[1]), "+f"(d[2]), "+f"(d[3])
        : "r"(a[0]), "r"(a[1]), "r"(a[2]), "r"(a[3]), "r"(b0), "r"(b1));
}
__device__ __forceinline__ uint32_t bf2pack(float a, float b) {
    __nv_bfloat162 t;
    t.x = __float2bfloat16(a);
    t.y = __float2bfloat16(b);
    return *(uint32_t*)&t;
}

// =============================================================================
// Kernel 1: prep — HBM-bound over 512 MB of x; writes bf16 hi/lo splits directly
// =============================================================================
__global__ __launch_bounds__(64) void prep_kernel(
    const float* __restrict__ x, const float* __restrict__ W1,
    const float* __restrict__ W2, const float* __restrict__ W3)
{
    __shared__ float sx[64][65];
    __shared__ float l1[64];
    __shared__ float sW1[64], sW3[64];

    const int t = threadIdx.x;
    sW1[t] = W1[t];
    sW3[t] = W3[t];

    const float4* x4 = reinterpret_cast<const float4*>(x) + (size_t)blockIdx.x * 1024;
#pragma unroll
    for (int i = 0; i < 16; i++) {
        int idx = i * 64 + t;
        float4 v = x4[idx];
        int f = idx >> 4;
        int c = (idx & 15) * 4;
        sx[f][c + 0] = v.x; sx[f][c + 1] = v.y;
        sx[f][c + 2] = v.z; sx[f][c + 3] = v.w;
    }
    __syncthreads();

    float acc = 0.f;
#pragma unroll
    for (int k = 0; k < 64; k++) acc += sx[t][k] * sW1[k];
    l1[t] = acc;

    float r = 0.f;
#pragma unroll
    for (int f = 0; f < 64; f++) r += sW3[f] * sx[f][t];

    __syncthreads();

    float l = 0.f;
#pragma unroll
    for (int f = 0; f < 64; f++) l += l1[f] * W2[f * 64 + t];

    size_t o = (size_t)blockIdx.x * 64 + t;
    __nv_bfloat16 lh = __float2bfloat16(l);
    __nv_bfloat16 rh = __float2bfloat16(r);
    g_lh_h[o] = lh;
    g_lh_l[o] = __float2bfloat16(l - __bfloat162float(lh));
    g_rh_h[o] = rh;
    g_rh_l[o] = __float2bfloat16(r - __bfloat162float(rh));
}

// =============================================================================
// Kernel 2a: split Vs into bf16 hi/lo
// =============================================================================
__global__ __launch_bounds__(256) void split_vs(const float* __restrict__ Vs)
{
    int i = (blockIdx.x * 256 + threadIdx.x) * 4;
    float4 v = *(const float4*)&Vs[i];
    __nv_bfloat16 h0 = __float2bfloat16(v.x), h1 = __float2bfloat16(v.y);
    __nv_bfloat16 h2 = __float2bfloat16(v.z), h3 = __float2bfloat16(v.w);
    uint32_t hw0 = bf2pack(v.x, v.y), hw1 = bf2pack(v.z, v.w);
    uint32_t lw0 = bf2pack(v.x - __bfloat162float(h0), v.y - __bfloat162float(h1));
    uint32_t lw1 = bf2pack(v.z - __bfloat162float(h2), v.w - __bfloat162float(h3));
    *(uint2*)&g_Vh[i] = make_uint2(hw0, hw1);
    *(uint2*)&g_Vl[i] = make_uint2(lw0, lw1);
}

// =============================================================================
// Kernel 2b: transpose bias once: bsT[m][n] = bs[n][m]
// =============================================================================
__global__ __launch_bounds__(256) void transpose_bs(const float* __restrict__ bs)
{
    __shared__ float t[32][33];
    const int tx = threadIdx.x, ty = threadIdx.y;
    const int x0 = blockIdx.x * 32, y0 = blockIdx.y * 32;
#pragma unroll
    for (int r = 0; r < 4; r++)
        t[ty + r * 8][tx] = bs[(size_t)(y0 + ty + r * 8) * NN + x0 + tx];
    __syncthreads();
#pragma unroll
    for (int r = 0; r < 4; r++)
        g_bsT[(size_t)(x0 + ty + r * 8) * NN + y0 + tx] = t[tx][ty + r * 8];
}

// =============================================================================
// Kernel 3: product via tensor cores.
// Gt[b,m,n] = sigmoid( rhs[b,m,:]·lhs[b,n,:] + bsT[m,n] ), split to bf16 hi/lo.
// A = rhs (K-major), B = lhs (K-major), K=64, 3-term split. 64 KB smem, 1 load.
// =============================================================================
#define PM_SMEM 65536

__global__ void __launch_bounds__(256, 2) product_mma()
{
    extern __shared__ __align__(1024) char dsm[];
    const uint32_t sb = smem_u32(dsm);

    const int tid  = threadIdx.x;
    const int lane = tid & 31;
    const int w    = tid >> 5;
    const int b    = blockIdx.z;
    const int m0   = blockIdx.y * 128;
    const int n0   = blockIdx.x * 128;

    const int wi0 = (w >> 1) * 32;   // warp row offset (m)
    const int wm0 = (w & 1) * 64;    // warp col offset (n)

    const int ld_row = tid >> 3;
    const int ld_c   = tid & 7;

    const int a_row  = wi0 + (lane & 15);
    const int a_half = lane >> 4;
    const int b_nB   = (lane & 7) + ((lane >> 4) << 3);
    const int b_half = (lane >> 3) & 1;
    const int swz    = lane & 7;

    // load all four 16 KB tiles (Ah, Al, Bh, Bl)
#pragma unroll
    for (int it = 0; it < 4; it++) {
        int row = ld_row + it * 32;
        uint32_t soff = row * 128 + ((ld_c ^ (row & 7)) * 16);
        size_t aoff = ((size_t)b * NN + m0 + row) * 64 + ld_c * 8;
        size_t boff = ((size_t)b * NN + n0 + row) * 64 + ld_c * 8;
        cp16(sb + soff,         g_rh_h + aoff);
        cp16(sb + 16384 + soff, g_rh_l + aoff);
        cp16(sb + 32768 + soff, g_lh_h + boff);
        cp16(sb + 49152 + soff, g_lh_l + boff);
    }
    cp_commit();

    float acc[2][8][4];
#pragma unroll
    for (int mt = 0; mt < 2; mt++)
#pragma unroll
        for (int j = 0; j < 8; j++)
#pragma unroll
            for (int q = 0; q < 4; q++) acc[mt][j][q] = 0.f;

    cp_wait0();
    __syncthreads();

#pragma unroll
    for (int ks = 0; ks < 4; ks++) {
        uint32_t ah[2][4], al[2][4];
#pragma unroll
        for (int mt = 0; mt < 2; mt++) {
            uint32_t off = (a_row + mt * 16) * 128 + (((2 * ks + a_half) ^ swz) * 16);
            LDSM_X4(ah[mt][0], ah[mt][1], ah[mt][2], ah[mt][3], sb + off);
            LDSM_X4(al[mt][0], al[mt][1], al[mt][2], al[mt][3], sb + 16384 + off);
        }
#pragma unroll
        for (int nt = 0; nt < 4; nt++) {
            uint32_t bh[4], bl[4];
            uint32_t off = (wm0 + nt * 16 + b_nB) * 128 + (((2 * ks + b_half) ^ swz) * 16);
            LDSM_X4(bh[0], bh[1], bh[2], bh[3], sb + 32768 + off);
            LDSM_X4(bl[0], bl[1], bl[2], bl[3], sb + 49152 + off);
#pragma unroll
            for (int mt = 0; mt < 2; mt++) {
                mma16816(acc[mt][nt * 2 + 0], ah[mt], bh[0], bh[1]);
                mma16816(acc[mt][nt * 2 + 1], ah[mt], bh[2], bh[3]);
                mma16816(acc[mt][nt * 2 + 0], ah[mt], bl[0], bl[1]);
                mma16816(acc[mt][nt * 2 + 1], ah[mt], bl[2], bl[3]);
                mma16816(acc[mt][nt * 2 + 0], al[mt], bh[0], bh[1]);
                mma16816(acc[mt][nt * 2 + 1], al[mt], bh[2], bh[3]);
            }
        }
    }

    // epilogue: + bsT, sigmoid, split, store
#pragma unroll
    for (int mt = 0; mt < 2; mt++) {
        int r0 = m0 + wi0 + mt * 16 + (lane >> 2);
#pragma unroll
        for (int nt = 0; nt < 4; nt++)
#pragma unroll
            for (int h = 0; h < 2; h++) {
                int j = nt * 2 + h;
                int cn = n0 + wm0 + nt * 16 + h * 8 + (lane & 3) * 2;
#pragma unroll
                for (int rr = 0; rr < 2; rr++) {
                    int row = r0 + rr * 8;
                    float p0 = acc[mt][j][rr * 2 + 0];
                    float p1 = acc[mt][j][rr * 2 + 1];
                    float2 bb = *(const float2*)&g_bsT[(size_t)row * NN + cn];
                    float g0 = 1.f / (1.f + __expf(-(p0 + bb.x)));
                    float g1 = 1.f / (1.f + __expf(-(p1 + bb.y)));
                    __nv_bfloat16 h0 = __float2bfloat16(g0);
                    __nv_bfloat16 h1 = __float2bfloat16(g1);
                    __nv_bfloat162 hh; hh.x = h0; hh.y = h1;
                    uint32_t lw = bf2pack(g0 - __bfloat162float(h0),
                                          g1 - __bfloat162float(h1));
                    size_t o = ((size_t)b << 20) + ((size_t)row << 10) + cn;
                    *(uint32_t*)&g_Gh[o] = *(uint32_t*)&hh;
                    *(uint32_t*)&g_Gl[o] = lw;
                }
            }
    }
}

// =============================================================================
// Kernel 4: fused 3-pass tensor-core GEMM via mma.sync.
// S[b,i,m] = sum_n Vs[i,n]*Gt[b,m,n];  D = Vh·Gh + Vh·Gl + Vl·Gh
// 3-stage cp.async ring (192 KB), 16 x 64-k stages. Epilogue writes exp(S)
// and per-CTA column partial sums (deterministic, no atomics).
// =============================================================================
#define GF_STAGES 3
#define GF_STAGE_BYTES 65536
#define GF_SMEM (GF_STAGES * GF_STAGE_BYTES)   // 192 KB

__global__ void __launch_bounds__(256, 1) gemm_fused(float* __restrict__ S)
{
    extern __shared__ __align__(1024) char dsm[];
    __shared__ float wsum[8][64];
    const uint32_t sm0 = smem_u32(dsm);

    const int tid  = threadIdx.x;
    const int lane = tid & 31;
    const int w    = tid >> 5;
    const int b    = blockIdx.z;
    const int i0g  = blockIdx.y * 128;
    const int m0   = blockIdx.x * 128;

    const int wi0 = (w >> 1) * 32;
    const int wm0 = (w & 1) * 64;

    const int ld_row = tid >> 3;
    const int ld_c   = tid & 7;

    const int a_row  = wi0 + (lane & 15);
    const int a_half = lane >> 4;
    const int b_nB   = (lane & 7) + ((lane >> 4) << 3);
    const int b_half = (lane >> 3) & 1;
    const int swz    = lane & 7;

    float acc[2][8][4];
#pragma unroll
    for (int mt = 0; mt < 2; mt++)
#pragma unroll
        for (int j = 0; j < 8; j++)
#pragma unroll
            for (int q = 0; q < 4; q++) acc[mt][j][q] = 0.f;

    auto load_stage = [&](int kk) {
        const int k0 = kk * 64;
        const uint32_t sb = sm0 + (kk % GF_STAGES) * GF_STAGE_BYTES;
#pragma unroll
        for (int it = 0; it < 4; it++) {
            int row = ld_row + it * 32;
            uint32_t soff = row * 128 + ((ld_c ^ (row & 7)) * 16);
            size_t aoff = (((size_t)(i0g + row)) << 10) + k0 + ld_c * 8;
            size_t boff = ((size_t)b << 20) + (((size_t)(m0 + row)) << 10) + k0 + ld_c * 8;
            cp16(sb + soff,         g_Vh + aoff);
            cp16(sb + 16384 + soff, g_Vl + aoff);
            cp16(sb + 32768 + soff, g_Gh + boff);
            cp16(sb + 49152 + soff, g_Gl + boff);
        }
        cp_commit();
    };

    load_stage(0);
    load_stage(1);

#pragma unroll 1
    for (int kk = 0; kk < 16; kk++) {
        if (kk + 2 < 16) load_stage(kk + 2);
        else cp_commit();
        cp_wait2();
        __syncthreads();

        const uint32_t sb = sm0 + (kk % GF_STAGES) * GF_STAGE_BYTES;

#pragma unroll
        for (int ks = 0; ks < 4; ks++) {
            uint32_t ah[2][4], al[2][4];
#pragma unroll
            for (int mt = 0; mt < 2; mt++) {
                uint32_t off = (a_row + mt * 16) * 128
                             + (((2 * ks + a_half) ^ swz) * 16);
                LDSM_X4(ah[mt][0], ah[mt][1], ah[mt][2], ah[mt][3], sb + off);
                LDSM_X4(al[mt][0], al[mt][1], al[mt][2], al[mt][3], sb + 16384 + off);
            }
#pragma unroll
            for (int nt = 0; nt < 4; nt++) {
                uint32_t bh[4], bl[4];
                uint32_t off = (wm0 + nt * 16 + b_nB) * 128
                             + (((2 * ks + b_half) ^ swz) * 16);
                LDSM_X4(bh[0], bh[1], bh[2], bh[3], sb + 32768 + off);
                LDSM_X4(bl[0], bl[1], bl[2], bl[3], sb + 49152 + off);
#pragma unroll
                for (int mt = 0; mt < 2; mt++) {
                    mma16816(acc[mt][nt * 2 + 0], ah[mt], bh[0], bh[1]);
                    mma16816(acc[mt][nt * 2 + 1], ah[mt], bh[2], bh[3]);
                    mma16816(acc[mt][nt * 2 + 0], ah[mt], bl[0], bl[1]);
                    mma16816(acc[mt][nt * 2 + 1], ah[mt], bl[2], bl[3]);
                    mma16816(acc[mt][nt * 2 + 0], al[mt], bh[0], bh[1]);
                    mma16816(acc[mt][nt * 2 + 1], al[mt], bh[2], bh[3]);
                }
            }
        }
        __syncthreads();
    }

    // epilogue: write exp(S) + accumulate column partial sums
    float cs[16];
#pragma unroll
    for (int i = 0; i < 16; i++) cs[i] = 0.f;

    float* Sb = S + ((size_t)b << 20);
#pragma unroll
    for (int mt = 0; mt < 2; mt++) {
        int r0 = i0g + wi0 + mt * 16 + (lane >> 2);
#pragma unroll
        for (int nt = 0; nt < 4; nt++)
#pragma unroll
            for (int h = 0; h < 2; h++) {
                int j = nt * 2 + h;
                int cm = m0 + wm0 + nt * 16 + h * 8 + (lane & 3) * 2;
                float e0 = __expf(acc[mt][j][0]);
                float e1 = __expf(acc[mt][j][1]);
                float e2 = __expf(acc[mt][j][2]);
                float e3 = __expf(acc[mt][j][3]);
                *(float2*)&Sb[((size_t)r0 << 10) + cm] = make_float2(e0, e1);
                *(float2*)&Sb[((size_t)(r0 + 8) << 10) + cm] = make_float2(e2, e3);
                cs[nt * 4 + h * 2 + 0] += e0 + e2;
                cs[nt * 4 + h * 2 + 1] += e1 + e3;
            }
    }
#pragma unroll
    for (int i = 0; i < 16; i++) {
        cs[i] += __shfl_xor_sync(0xffffffffu, cs[i], 4);
        cs[i] += __shfl_xor_sync(0xffffffffu, cs[i], 8);
        cs[i] += __shfl_xor_sync(0xffffffffu, cs[i], 16);
    }
    if (lane < 4) {
#pragma unroll
        for (int nt = 0; nt < 4; nt++)
#pragma unroll
            for (int h = 0; h < 2; h++) {
                wsum[w][nt * 16 + h * 8 + lane * 2 + 0] = cs[nt * 4 + h * 2 + 0];
                wsum[w][nt * 16 + h * 8 + lane * 2 + 1] = cs[nt * 4 + h * 2 + 1];
            }
    }
    __syncthreads();
    if (tid < 128) {
        int h = tid >> 6, c = tid & 63;
        float s = wsum[h][c] + wsum[2 + h][c] + wsum[4 + h][c] + wsum[6 + h][c];
        g_part[blockIdx.y][((size_t)b << 10) + m0 + h * 64 + c] = s;
    }
}

// =============================================================================
// Kernel 5: reduce per-i-tile partials -> 1/colsum
// =============================================================================
__global__ __launch_bounds__(256) void reduce_part()
{
    int t = blockIdx.x * 256 + threadIdx.x;   // 0..32767 = b*1024 + m
    float s = 0.f;
#pragma unroll
    for (int q = 0; q < 8; q++) s += g_part[q][t];
    g_cinv[t] = __fdividef(1.f, s);
}

// =============================================================================
// Kernel 6: normalize in place: out = expS * (1/colsum)
// =============================================================================
__global__ __launch_bounds__(256) void normalize_kernel(float* __restrict__ S)
{
    const int bi = blockIdx.x;
    const int b = bi >> 10;
    const int m = threadIdx.x * 4;
    size_t base = (size_t)bi * NN + m;

    float4 v  = *(const float4*)&S[base];
    float4 iv = *(const float4*)&g_cinv[b * NN + m];
    float4 o;
    o.x = v.x * iv.x;
    o.y = v.y * iv.y;
    o.z = v.z * iv.z;
    o.w = v.w * iv.w;
    *(float4*)&S[base] = o;
}

// =============================================================================
extern "C" void kernel_launch(void* const* d_in, const int* in_sizes, int n_in,
                              void* d_out, int out_size)
{
    (void)in_sizes; (void)n_in; (void)out_size;
    const float* x  = (const float*)d_in[0];
    const float* W1 = (const float*)d_in[1];
    const float* W2 = (const float*)d_in[2];
    const float* W3 = (const float*)d_in[3];
    const float* bs = (const float*)d_in[4];
    const float* Vs = (const float*)d_in[5];
    float* out = (float*)d_out;

    cudaFuncSetAttribute(product_mma, cudaFuncAttributeMaxDynamicSharedMemorySize,
                         PM_SMEM);
    cudaFuncSetAttribute(gemm_fused, cudaFuncAttributeMaxDynamicSharedMemorySize,
                         GF_SMEM);

    prep_kernel<<<BB * NN, 64>>>(x, W1, W2, W3);
    split_vs<<<NN * NN / 1024, 256>>>(Vs);
    transpose_bs<<<dim3(32, 32), dim3(32, 8)>>>(bs);
    product_mma<<<dim3(8, 8, BB), 256, PM_SMEM>>>();
    gemm_fused<<<dim3(8, 8, BB), 256, GF_SMEM>>>(out);
    reduce_part<<<128, 256>>>();
    normalize_kernel<<<BB * NN, 256>>>(out);
}

// round 9
// speedup vs baseline: 2.5838x; 1.1333x over previous
#include <cuda_runtime.h>
#include <cuda_bf16.h>
#include <cstdint>

#define BB 32
#define NN 1024
#define TT 64

typedef unsigned long long ull;

// ---------------- scratch (device globals) -----------------------------------
__device__ __nv_bfloat16 g_lh_h[BB * NN * TT];            // 4 MB  lhs hi (b,n,t)
__device__ __nv_bfloat16 g_lh_l[BB * NN * TT];            // 4 MB  lhs lo
__device__ __nv_bfloat16 g_rh_h[BB * NN * TT];            // 4 MB  rhs hi (b,m,t)
__device__ __nv_bfloat16 g_rh_l[BB * NN * TT];            // 4 MB  rhs lo
__device__ unsigned char g_Vq_h[NN * NN];                 // 1 MB  V hi byte (s8)
__device__ unsigned char g_Vq_l[NN * NN];                 // 1 MB  V lo byte (s8, centered)
__device__ unsigned char g_Gq_h[(size_t)BB << 20];        // 32 MB G hi byte (u8), (b,m,n)
__device__ unsigned char g_Gq_l[(size_t)BB << 20];        // 32 MB G lo byte (u8)
__device__ float         g_bsT[NN * NN];                  // 4 MB  bs transposed
__device__ float         g_part[8][BB * NN];              // 1 MB  per-i-tile col partials
__device__ float         g_cinv[BB * NN];                 // per-(b,m) 1/colsum
__device__ unsigned int  g_vmax_u;                        // max|Vs| as float bits

// ---------------- smem / cp.async / mma helpers (all sm_80+ legal) ------------
__device__ __forceinline__ uint32_t smem_u32(const void* p) {
    uint32_t a;
    asm("{ .reg .u64 t; cvta.to.shared.u64 t, %1; cvt.u32.u64 %0, t; }"
        : "=r"(a) : "l"(p));
    return a;
}
__device__ __forceinline__ void cp16(uint32_t dst, const void* src) {
    asm volatile("cp.async.cg.shared.global [%0], [%1], 16;" :: "r"(dst), "l"(src));
}
__device__ __forceinline__ void cp_commit() {
    asm volatile("cp.async.commit_group;" ::: "memory");
}
__device__ __forceinline__ void cp_wait3() {
    asm volatile("cp.async.wait_group 3;" ::: "memory");
}
__device__ __forceinline__ void cp_wait0() {
    asm volatile("cp.async.wait_group 0;" ::: "memory");
}
#define LDSM_X4(r0, r1, r2, r3, addr)                                           \
    asm volatile("ldmatrix.sync.aligned.m8n8.x4.shared.b16 {%0,%1,%2,%3}, [%4];" \
        : "=r"(r0), "=r"(r1), "=r"(r2), "=r"(r3) : "r"(addr))

__device__ __forceinline__ void mma16816(float* d, const uint32_t* a,
                                         uint32_t b0, uint32_t b1) {
    asm volatile(
        "mma.sync.aligned.m16n8k16.row.col.f32.bf16.bf16.f32 "
        "{%0,%1,%2,%3}, {%4,%5,%6,%7}, {%8,%9}, {%0,%1,%2,%3};"
        : "+f"(d[0]), "+f"(d[1]), "+f"(d[2]), "+f"(d[3])
        : "r"(a[0]), "r"(a[1]), "r"(a[2]), "r"(a[3]), "r"(b0), "r"(b1));
}
// int8 x uint8 -> s32, m16n8k32 (4096 MAC/instr = 2x HMMA.16816)
#define IMMA(d, a, b0, b1)                                                      \
    asm volatile(                                                               \
        "mma.sync.aligned.m16n8k32.row.col.s32.s8.u8.s32 "                      \
        "{%0,%1,%2,%3}, {%4,%5,%6,%7}, {%8,%9}, {%0,%1,%2,%3};"                 \
        : "+r"((d)[0]), "+r"((d)[1]), "+r"((d)[2]), "+r"((d)[3])                \
        : "r"((a)[0]), "r"((a)[1]), "r"((a)[2]), "r"((a)[3]), "r"(b0), "r"(b1))

// =============================================================================
// Kernel 1: prep — HBM-bound over 512 MB of x; writes bf16 hi/lo splits
// =============================================================================
__global__ __launch_bounds__(64) void prep_kernel(
    const float* __restrict__ x, const float* __restrict__ W1,
    const float* __restrict__ W2, const float* __restrict__ W3)
{
    __shared__ float sx[64][65];
    __shared__ float l1[64];
    __shared__ float sW1[64], sW3[64];

    const int t = threadIdx.x;
    sW1[t] = W1[t];
    sW3[t] = W3[t];

    const float4* x4 = reinterpret_cast<const float4*>(x) + (size_t)blockIdx.x * 1024;
#pragma unroll
    for (int i = 0; i < 16; i++) {
        int idx = i * 64 + t;
        float4 v = x4[idx];
        int f = idx >> 4;
        int c = (idx & 15) * 4;
        sx[f][c + 0] = v.x; sx[f][c + 1] = v.y;
        sx[f][c + 2] = v.z; sx[f][c + 3] = v.w;
    }
    __syncthreads();

    float acc = 0.f;
#pragma unroll
    for (int k = 0; k < 64; k++) acc += sx[t][k] * sW1[k];
    l1[t] = acc;

    float r = 0.f;
#pragma unroll
    for (int f = 0; f < 64; f++) r += sW3[f] * sx[f][t];

    __syncthreads();

    float l = 0.f;
#pragma unroll
    for (int f = 0; f < 64; f++) l += l1[f] * W2[f * 64 + t];

    size_t o = (size_t)blockIdx.x * 64 + t;
    __nv_bfloat16 lh = __float2bfloat16(l);
    __nv_bfloat16 rh = __float2bfloat16(r);
    g_lh_h[o] = lh;
    g_lh_l[o] = __float2bfloat16(l - __bfloat162float(lh));
    g_rh_h[o] = rh;
    g_rh_l[o] = __float2bfloat16(r - __bfloat162float(rh));
}

// =============================================================================
// Kernel 2a/2b/2c: Vmax reduction (deterministic via atomicMax on bits) + quant
// =============================================================================
__global__ void zero_vmax() { g_vmax_u = 0u; }

__global__ __launch_bounds__(256) void vmax_kernel(const float* __restrict__ Vs)
{
    int i = (blockIdx.x * 256 + threadIdx.x) * 4;
    float4 v = *(const float4*)&Vs[i];
    float m = fmaxf(fmaxf(fabsf(v.x), fabsf(v.y)), fmaxf(fabsf(v.z), fabsf(v.w)));
#pragma unroll
    for (int s = 16; s > 0; s >>= 1)
        m = fmaxf(m, __shfl_xor_sync(0xffffffffu, m, s));
    if ((threadIdx.x & 31) == 0)
        atomicMax(&g_vmax_u, __float_as_uint(m));
}

__global__ __launch_bounds__(256) void quant_vs(const float* __restrict__ Vs)
{
    const float vmax = __uint_as_float(g_vmax_u);
    const float inv_s = 32639.f / fmaxf(vmax, 1e-30f);
    int i = (blockIdx.x * 256 + threadIdx.x) * 4;
    float4 v = *(const float4*)&Vs[i];
    uint32_t hp = 0, lp = 0;
    float vv[4] = {v.x, v.y, v.z, v.w};
#pragma unroll
    for (int j = 0; j < 4; j++) {
        int q = __float2int_rn(vv[j] * inv_s);
        q = max(-32768, min(32639, q));
        int vl = ((q + 128) & 255) - 128;        // centered low byte (s8)
        int vh = (q - vl) >> 8;                  // high byte (s8)
        hp |= ((uint32_t)(vh & 255)) << (j * 8);
        lp |= ((uint32_t)(vl & 255)) << (j * 8);
    }
    *(uint32_t*)&g_Vq_h[i] = hp;
    *(uint32_t*)&g_Vq_l[i] = lp;
}

// =============================================================================
// Kernel 2d: transpose bias once: bsT[m][n] = bs[n][m]
// =============================================================================
__global__ __launch_bounds__(256) void transpose_bs(const float* __restrict__ bs)
{
    __shared__ float t[32][33];
    const int tx = threadIdx.x, ty = threadIdx.y;
    const int x0 = blockIdx.x * 32, y0 = blockIdx.y * 32;
#pragma unroll
    for (int r = 0; r < 4; r++)
        t[ty + r * 8][tx] = bs[(size_t)(y0 + ty + r * 8) * NN + x0 + tx];
    __syncthreads();
#pragma unroll
    for (int r = 0; r < 4; r++)
        g_bsT[(size_t)(x0 + ty + r * 8) * NN + y0 + tx] = t[tx][ty + r * 8];
}

// =============================================================================
// Kernel 3: product via bf16 tensor cores; epilogue sigmoid -> 16-bit fixed-
// point split Gq = 256*Gh + Gl (u8 arrays), G = Gq/65535.
// =============================================================================
#define PM_SMEM 65536

__global__ void __launch_bounds__(256, 2) product_mma()
{
    extern __shared__ __align__(1024) char dsm[];
    const uint32_t sb = smem_u32(dsm);

    const int tid  = threadIdx.x;
    const int lane = tid & 31;
    const int w    = tid >> 5;
    const int b    = blockIdx.z;
    const int m0   = blockIdx.y * 128;
    const int n0   = blockIdx.x * 128;

    const int wi0 = (w >> 1) * 32;
    const int wm0 = (w & 1) * 64;

    const int ld_row = tid >> 3;
    const int ld_c   = tid & 7;

    const int a_row  = wi0 + (lane & 15);
    const int a_half = lane >> 4;
    const int b_nB   = (lane & 7) + ((lane >> 4) << 3);
    const int b_half = (lane >> 3) & 1;
    const int swz    = lane & 7;

#pragma unroll
    for (int it = 0; it < 4; it++) {
        int row = ld_row + it * 32;
        uint32_t soff = row * 128 + ((ld_c ^ (row & 7)) * 16);
        size_t aoff = ((size_t)b * NN + m0 + row) * 64 + ld_c * 8;
        size_t boff = ((size_t)b * NN + n0 + row) * 64 + ld_c * 8;
        cp16(sb + soff,         g_rh_h + aoff);
        cp16(sb + 16384 + soff, g_rh_l + aoff);
        cp16(sb + 32768 + soff, g_lh_h + boff);
        cp16(sb + 49152 + soff, g_lh_l + boff);
    }
    cp_commit();

    float acc[2][8][4];
#pragma unroll
    for (int mt = 0; mt < 2; mt++)
#pragma unroll
        for (int j = 0; j < 8; j++)
#pragma unroll
            for (int q = 0; q < 4; q++) acc[mt][j][q] = 0.f;

    cp_wait0();
    __syncthreads();

#pragma unroll
    for (int ks = 0; ks < 4; ks++) {
        uint32_t ah[2][4], al[2][4];
#pragma unroll
        for (int mt = 0; mt < 2; mt++) {
            uint32_t off = (a_row + mt * 16) * 128 + (((2 * ks + a_half) ^ swz) * 16);
            LDSM_X4(ah[mt][0], ah[mt][1], ah[mt][2], ah[mt][3], sb + off);
            LDSM_X4(al[mt][0], al[mt][1], al[mt][2], al[mt][3], sb + 16384 + off);
        }
#pragma unroll
        for (int nt = 0; nt < 4; nt++) {
            uint32_t bh[4], bl[4];
            uint32_t off = (wm0 + nt * 16 + b_nB) * 128 + (((2 * ks + b_half) ^ swz) * 16);
            LDSM_X4(bh[0], bh[1], bh[2], bh[3], sb + 32768 + off);
            LDSM_X4(bl[0], bl[1], bl[2], bl[3], sb + 49152 + off);
#pragma unroll
            for (int mt = 0; mt < 2; mt++) {
                mma16816(acc[mt][nt * 2 + 0], ah[mt], bh[0], bh[1]);
                mma16816(acc[mt][nt * 2 + 1], ah[mt], bh[2], bh[3]);
                mma16816(acc[mt][nt * 2 + 0], ah[mt], bl[0], bl[1]);
                mma16816(acc[mt][nt * 2 + 1], ah[mt], bl[2], bl[3]);
                mma16816(acc[mt][nt * 2 + 0], al[mt], bh[0], bh[1]);
                mma16816(acc[mt][nt * 2 + 1], al[mt], bh[2], bh[3]);
            }
        }
    }

    // epilogue: + bsT, sigmoid, 16-bit quantize, byte-split store
#pragma unroll
    for (int mt = 0; mt < 2; mt++) {
        int r0 = m0 + wi0 + mt * 16 + (lane >> 2);
#pragma unroll
        for (int nt = 0; nt < 4; nt++)
#pragma unroll
            for (int h = 0; h < 2; h++) {
                int j = nt * 2 + h;
                int cn = n0 + wm0 + nt * 16 + h * 8 + (lane & 3) * 2;
#pragma unroll
                for (int rr = 0; rr < 2; rr++) {
                    int row = r0 + rr * 8;
                    float p0 = acc[mt][j][rr * 2 + 0];
                    float p1 = acc[mt][j][rr * 2 + 1];
                    float2 bb = *(const float2*)&g_bsT[(size_t)row * NN + cn];
                    float g0 = 1.f / (1.f + __expf(-(p0 + bb.x)));
                    float g1 = 1.f / (1.f + __expf(-(p1 + bb.y)));
                    uint32_t q0 = __float2uint_rn(g0 * 65535.f);
                    uint32_t q1 = __float2uint_rn(g1 * 65535.f);
                    size_t o = ((size_t)b << 20) + ((size_t)row << 10) + cn;
                    *(unsigned short*)&g_Gq_h[o] =
                        (unsigned short)((q0 >> 8) | ((q1 >> 8) << 8));
                    *(unsigned short*)&g_Gq_l[o] =
                        (unsigned short)((q0 & 255) | ((q1 & 255) << 8));
                }
            }
    }
}

// =============================================================================
// Kernel 4: int8 tensor-core GEMM.
// S[b,i,m] = sum_n V[i,n]*G[b,m,n]
//   = s*c*( 65536*Sum(Vh*Gh) + 256*(Sum(Vh*Gl)+Sum(Vl*Gh)) )   [VlGl dropped]
// 128x128 CTA tile, 4-stage cp.async ring (32 KB/stage), exact s32 accum.
// Epilogue: exp(S) + per-CTA column partial sums.
// =============================================================================
#define GI_STAGES 4
#define GI_STAGE_BYTES 32768
#define GI_SMEM (GI_STAGES * GI_STAGE_BYTES)   // 128 KB

__global__ void __launch_bounds__(256, 1) gemm_i8(float* __restrict__ S)
{
    extern __shared__ __align__(1024) char dsm[];
    __shared__ float wsum[8][64];
    const uint32_t sm0 = smem_u32(dsm);

    const int tid  = threadIdx.x;
    const int lane = tid & 31;
    const int w    = tid >> 5;
    const int b    = blockIdx.z;
    const int i0g  = blockIdx.y * 128;
    const int m0   = blockIdx.x * 128;

    const int wi0 = (w >> 1) * 32;
    const int wm0 = (w & 1) * 64;

    // ldmatrix bases (64-byte rows, swizzle = row&3 on 16B chunks)
    const int a_row  = wi0 + (lane & 15);
    const int a_half = lane >> 4;
    const int aswz   = a_row & 3;
    const int b_nB   = (lane & 7) + ((lane >> 4) << 3);
    const int b_half = (lane >> 3) & 1;
    const int bswz   = b_nB & 3;

    int acc1[2][8][4], acc2[2][8][4];
#pragma unroll
    for (int mt = 0; mt < 2; mt++)
#pragma unroll
        for (int j = 0; j < 8; j++)
#pragma unroll
            for (int q = 0; q < 4; q++) { acc1[mt][j][q] = 0; acc2[mt][j][q] = 0; }

    const int ld_r  = tid >> 1;
    const int ld_c0 = (tid & 1) * 2;

    auto load_stage = [&](int kk) {
        const int k0 = kk * 64;
        const uint32_t sb = sm0 + (kk & 3) * GI_STAGE_BYTES;
        size_t aoff = (size_t)(i0g + ld_r) * 1024 + k0;
        size_t boff = ((size_t)b << 20) + (size_t)(m0 + ld_r) * 1024 + k0;
#pragma unroll
        for (int cc = 0; cc < 2; cc++) {
            int c = ld_c0 + cc;
            uint32_t dsto = ld_r * 64 + ((c ^ (ld_r & 3)) * 16);
            cp16(sb + dsto,          g_Vq_h + aoff + c * 16);
            cp16(sb + 8192 + dsto,   g_Vq_l + aoff + c * 16);
            cp16(sb + 16384 + dsto,  g_Gq_h + boff + c * 16);
            cp16(sb + 24576 + dsto,  g_Gq_l + boff + c * 16);
        }
        cp_commit();
    };

    load_stage(0);
    load_stage(1);
    load_stage(2);

#pragma unroll 1
    for (int kk = 0; kk < 16; kk++) {
        if (kk + 3 < 16) load_stage(kk + 3);
        else cp_commit();
        cp_wait3();
        __syncthreads();

        const uint32_t sb = sm0 + (kk & 3) * GI_STAGE_BYTES;

#pragma unroll
        for (int ks = 0; ks < 2; ks++) {
            uint32_t ah[2][4], al[2][4];
#pragma unroll
            for (int mt = 0; mt < 2; mt++) {
                uint32_t off = (a_row + mt * 16) * 64
                             + (((2 * ks + a_half) ^ aswz) * 16);
                LDSM_X4(ah[mt][0], ah[mt][1], ah[mt][2], ah[mt][3], sb + off);
                LDSM_X4(al[mt][0], al[mt][1], al[mt][2], al[mt][3], sb + 8192 + off);
            }
#pragma unroll
            for (int nt = 0; nt < 4; nt++) {
                uint32_t bh[4], bl[4];
                uint32_t off = (wm0 + nt * 16 + b_nB) * 64
                             + (((2 * ks + b_half) ^ bswz) * 16);
                LDSM_X4(bh[0], bh[1], bh[2], bh[3], sb + 16384 + off);
                LDSM_X4(bl[0], bl[1], bl[2], bl[3], sb + 24576 + off);
#pragma unroll
                for (int mt = 0; mt < 2; mt++) {
                    IMMA(acc1[mt][nt * 2 + 0], ah[mt], bh[0], bh[1]);
                    IMMA(acc1[mt][nt * 2 + 1], ah[mt], bh[2], bh[3]);
                    IMMA(acc2[mt][nt * 2 + 0], ah[mt], bl[0], bl[1]);
                    IMMA(acc2[mt][nt * 2 + 1], ah[mt], bl[2], bl[3]);
                    IMMA(acc2[mt][nt * 2 + 0], al[mt], bh[0], bh[1]);
                    IMMA(acc2[mt][nt * 2 + 1], al[mt], bh[2], bh[3]);
                }
            }
        }
        __syncthreads();
    }

    // epilogue: S = sc1*acc1 + sc2*acc2; write exp(S) + column partials
    const float s_scale = __uint_as_float(g_vmax_u) * (1.f / 32639.f);
    const float base = s_scale * (1.f / 65535.f);
    const float sc1 = base * 65536.f;
    const float sc2 = base * 256.f;

    float cs[16];
#pragma unroll
    for (int i = 0; i < 16; i++) cs[i] = 0.f;

    float* Sb = S + ((size_t)b << 20);
#pragma unroll
    for (int mt = 0; mt < 2; mt++) {
        int r0 = i0g + wi0 + mt * 16 + (lane >> 2);
#pragma unroll
        for (int nt = 0; nt < 4; nt++)
#pragma unroll
            for (int h = 0; h < 2; h++) {
                int j = nt * 2 + h;
                int cm = m0 + wm0 + nt * 16 + h * 8 + (lane & 3) * 2;
                float v0 = fmaf(sc1, (float)acc1[mt][j][0], sc2 * (float)acc2[mt][j][0]);
                float v1 = fmaf(sc1, (float)acc1[mt][j][1], sc2 * (float)acc2[mt][j][1]);
                float v2 = fmaf(sc1, (float)acc1[mt][j][2], sc2 * (float)acc2[mt][j][2]);
                float v3 = fmaf(sc1, (float)acc1[mt][j][3], sc2 * (float)acc2[mt][j][3]);
                float e0 = __expf(v0), e1 = __expf(v1);
                float e2 = __expf(v2), e3 = __expf(v3);
                *(float2*)&Sb[((size_t)r0 << 10) + cm] = make_float2(e0, e1);
                *(float2*)&Sb[((size_t)(r0 + 8) << 10) + cm] = make_float2(e2, e3);
                cs[nt * 4 + h * 2 + 0] += e0 + e2;
                cs[nt * 4 + h * 2 + 1] += e1 + e3;
            }
    }
#pragma unroll
    for (int i = 0; i < 16; i++) {
        cs[i] += __shfl_xor_sync(0xffffffffu, cs[i], 4);
        cs[i] += __shfl_xor_sync(0xffffffffu, cs[i], 8);
        cs[i] += __shfl_xor_sync(0xffffffffu, cs[i], 16);
    }
    if (lane < 4) {
#pragma unroll
        for (int nt = 0; nt < 4; nt++)
#pragma unroll
            for (int h = 0; h < 2; h++) {
                wsum[w][nt * 16 + h * 8 + lane * 2 + 0] = cs[nt * 4 + h * 2 + 0];
                wsum[w][nt * 16 + h * 8 + lane * 2 + 1] = cs[nt * 4 + h * 2 + 1];
            }
    }
    __syncthreads();
    if (tid < 128) {
        int h = tid >> 6, c = tid & 63;
        float s = wsum[h][c] + wsum[2 + h][c] + wsum[4 + h][c] + wsum[6 + h][c];
        g_part[blockIdx.y][((size_t)b << 10) + m0 + h * 64 + c] = s;
    }
}

// =============================================================================
// Kernel 5: reduce per-i-tile partials -> 1/colsum
// =============================================================================
__global__ __launch_bounds__(256) void reduce_part()
{
    int t = blockIdx.x * 256 + threadIdx.x;
    float s = 0.f;
#pragma unroll
    for (int q = 0; q < 8; q++) s += g_part[q][t];
    g_cinv[t] = __fdividef(1.f, s);
}

// =============================================================================
// Kernel 6: normalize in place: out = expS * (1/colsum)
// =============================================================================
__global__ __launch_bounds__(256) void normalize_kernel(float* __restrict__ S)
{
    const int bi = blockIdx.x;
    const int b = bi >> 10;
    const int m = threadIdx.x * 4;
    size_t base = (size_t)bi * NN + m;

    float4 v  = *(const float4*)&S[base];
    float4 iv = *(const float4*)&g_cinv[b * NN + m];
    float4 o;
    o.x = v.x * iv.x;
    o.y = v.y * iv.y;
    o.z = v.z * iv.z;
    o.w = v.w * iv.w;
    *(float4*)&S[base] = o;
}

// =============================================================================
extern "C" void kernel_launch(void* const* d_in, const int* in_sizes, int n_in,
                              void* d_out, int out_size)
{
    (void)in_sizes; (void)n_in; (void)out_size;
    const float* x  = (const float*)d_in[0];
    const float* W1 = (const float*)d_in[1];
    const float* W2 = (const float*)d_in[2];
    const float* W3 = (const float*)d_in[3];
    const float* bs = (const float*)d_in[4];
    const float* Vs = (const float*)d_in[5];
    float* out = (float*)d_out;

    cudaFuncSetAttribute(product_mma, cudaFuncAttributeMaxDynamicSharedMemorySize,
                         PM_SMEM);
    cudaFuncSetAttribute(gemm_i8, cudaFuncAttributeMaxDynamicSharedMemorySize,
                         GI_SMEM);

    prep_kernel<<<BB * NN, 64>>>(x, W1, W2, W3);
    zero_vmax<<<1, 1>>>();
    vmax_kernel<<<NN * NN / 1024, 256>>>(Vs);
    quant_vs<<<NN * NN / 1024, 256>>>(Vs);
    transpose_bs<<<dim3(32, 32), dim3(32, 8)>>>(bs);
    product_mma<<<dim3(8, 8, BB), 256, PM_SMEM>>>();
    gemm_i8<<<dim3(8, 8, BB), 256, GI_SMEM>>>(out);
    reduce_part<<<128, 256>>>();
    normalize_kernel<<<BB * NN, 256>>>(out);
}

// round 10
// speedup vs baseline: 2.6295x; 1.0177x over previous
#include <cuda_runtime.h>
#include <cuda_bf16.h>
#include <cstdint>

#define BB 32
#define NN 1024
#define TT 64

typedef unsigned long long ull;

// ---------------- scratch (device globals) -----------------------------------
__device__ __nv_bfloat16 g_lh_h[BB * NN * TT];            // 4 MB  lhs hi (b,n,t)
__device__ __nv_bfloat16 g_lh_l[BB * NN * TT];            // 4 MB  lhs lo
__device__ __nv_bfloat16 g_rh_h[BB * NN * TT];            // 4 MB  rhs hi (b,m,t)
__device__ __nv_bfloat16 g_rh_l[BB * NN * TT];            // 4 MB  rhs lo
__device__ unsigned char g_Vq_h[NN * NN];                 // 1 MB  V hi byte (s8)
__device__ unsigned char g_Vq_l[NN * NN];                 // 1 MB  V lo byte (s8, centered)
__device__ unsigned char g_Gq_h[(size_t)BB << 20];        // 32 MB G hi byte (u8), (b,m,n)
__device__ unsigned char g_Gq_l[(size_t)BB << 20];        // 32 MB G lo byte (u8)
__device__ float         g_bsT[NN * NN];                  // 4 MB  bs transposed
__device__ float         g_part[8][BB * NN];              // 1 MB  per-i-tile col partials
__device__ float         g_cinv[BB * NN];                 // per-(b,m) 1/colsum
__device__ unsigned int  g_vmax_u;                        // max|Vs| as float bits

// ---------------- smem / cp.async / mma helpers (all sm_80+ legal) ------------
__device__ __forceinline__ uint32_t smem_u32(const void* p) {
    uint32_t a;
    asm("{ .reg .u64 t; cvta.to.shared.u64 t, %1; cvt.u32.u64 %0, t; }"
        : "=r"(a) : "l"(p));
    return a;
}
__device__ __forceinline__ void cp16(uint32_t dst, const void* src) {
    asm volatile("cp.async.cg.shared.global [%0], [%1], 16;" :: "r"(dst), "l"(src));
}
__device__ __forceinline__ void cp_commit() {
    asm volatile("cp.async.commit_group;" ::: "memory");
}
__device__ __forceinline__ void cp_wait3() {
    asm volatile("cp.async.wait_group 3;" ::: "memory");
}
__device__ __forceinline__ void cp_wait1() {
    asm volatile("cp.async.wait_group 1;" ::: "memory");
}
#define LDSM_X4(r0, r1, r2, r3, addr)                                           \
    asm volatile("ldmatrix.sync.aligned.m8n8.x4.shared.b16 {%0,%1,%2,%3}, [%4];" \
        : "=r"(r0), "=r"(r1), "=r"(r2), "=r"(r3) : "r"(addr))

__device__ __forceinline__ void mma16816(float* d, const uint32_t* a,
                                         uint32_t b0, uint32_t b1) {
    asm volatile(
        "mma.sync.aligned.m16n8k16.row.col.f32.bf16.bf16.f32 "
        "{%0,%1,%2,%3}, {%4,%5,%6,%7}, {%8,%9}, {%0,%1,%2,%3};"
        : "+f"(d[0]), "+f"(d[1]), "+f"(d[2]), "+f"(d[3])
        : "r"(a[0]), "r"(a[1]), "r"(a[2]), "r"(a[3]), "r"(b0), "r"(b1));
}
// int8 x uint8 -> s32, m16n8k32
#define IMMA(d, a, b0, b1)                                                      \
    asm volatile(                                                               \
        "mma.sync.aligned.m16n8k32.row.col.s32.s8.u8.s32 "                      \
        "{%0,%1,%2,%3}, {%4,%5,%6,%7}, {%8,%9}, {%0,%1,%2,%3};"                 \
        : "+r"((d)[0]), "+r"((d)[1]), "+r"((d)[2]), "+r"((d)[3])                \
        : "r"((a)[0]), "r"((a)[1]), "r"((a)[2]), "r"((a)[3]), "r"(b0), "r"(b1))

// =============================================================================
// Kernel 1: prep — HBM-bound over 512 MB of x; writes bf16 hi/lo splits
// =============================================================================
__global__ __launch_bounds__(64) void prep_kernel(
    const float* __restrict__ x, const float* __restrict__ W1,
    const float* __restrict__ W2, const float* __restrict__ W3)
{
    __shared__ float sx[64][65];
    __shared__ float l1[64];
    __shared__ float sW1[64], sW3[64];

    const int t = threadIdx.x;
    sW1[t] = W1[t];
    sW3[t] = W3[t];

    const float4* x4 = reinterpret_cast<const float4*>(x) + (size_t)blockIdx.x * 1024;
#pragma unroll
    for (int i = 0; i < 16; i++) {
        int idx = i * 64 + t;
        float4 v = x4[idx];
        int f = idx >> 4;
        int c = (idx & 15) * 4;
        sx[f][c + 0] = v.x; sx[f][c + 1] = v.y;
        sx[f][c + 2] = v.z; sx[f][c + 3] = v.w;
    }
    __syncthreads();

    float acc = 0.f;
#pragma unroll
    for (int k = 0; k < 64; k++) acc += sx[t][k] * sW1[k];
    l1[t] = acc;

    float r = 0.f;
#pragma unroll
    for (int f = 0; f < 64; f++) r += sW3[f] * sx[f][t];

    __syncthreads();

    float l = 0.f;
#pragma unroll
    for (int f = 0; f < 64; f++) l += l1[f] * W2[f * 64 + t];

    size_t o = (size_t)blockIdx.x * 64 + t;
    __nv_bfloat16 lh = __float2bfloat16(l);
    __nv_bfloat16 rh = __float2bfloat16(r);
    g_lh_h[o] = lh;
    g_lh_l[o] = __float2bfloat16(l - __bfloat162float(lh));
    g_rh_h[o] = rh;
    g_rh_l[o] = __float2bfloat16(r - __bfloat162float(rh));
}

// =============================================================================
// Kernel 2: Vmax (deterministic) + 16-bit quant byte-split of Vs
// =============================================================================
__global__ void zero_vmax() { g_vmax_u = 0u; }

__global__ __launch_bounds__(256) void vmax_kernel(const float* __restrict__ Vs)
{
    int i = (blockIdx.x * 256 + threadIdx.x) * 4;
    float4 v = *(const float4*)&Vs[i];
    float m = fmaxf(fmaxf(fabsf(v.x), fabsf(v.y)), fmaxf(fabsf(v.z), fabsf(v.w)));
#pragma unroll
    for (int s = 16; s > 0; s >>= 1)
        m = fmaxf(m, __shfl_xor_sync(0xffffffffu, m, s));
    if ((threadIdx.x & 31) == 0)
        atomicMax(&g_vmax_u, __float_as_uint(m));
}

__global__ __launch_bounds__(256) void quant_vs(const float* __restrict__ Vs)
{
    const float vmax = __uint_as_float(g_vmax_u);
    const float inv_s = 32639.f / fmaxf(vmax, 1e-30f);
    int i = (blockIdx.x * 256 + threadIdx.x) * 4;
    float4 v = *(const float4*)&Vs[i];
    uint32_t hp = 0, lp = 0;
    float vv[4] = {v.x, v.y, v.z, v.w};
#pragma unroll
    for (int j = 0; j < 4; j++) {
        int q = __float2int_rn(vv[j] * inv_s);
        q = max(-32768, min(32639, q));
        int vl = ((q + 128) & 255) - 128;
        int vh = (q - vl) >> 8;
        hp |= ((uint32_t)(vh & 255)) << (j * 8);
        lp |= ((uint32_t)(vl & 255)) << (j * 8);
    }
    *(uint32_t*)&g_Vq_h[i] = hp;
    *(uint32_t*)&g_Vq_l[i] = lp;
}

// =============================================================================
// Kernel 2d: transpose bias once
// =============================================================================
__global__ __launch_bounds__(256) void transpose_bs(const float* __restrict__ bs)
{
    __shared__ float t[32][33];
    const int tx = threadIdx.x, ty = threadIdx.y;
    const int x0 = blockIdx.x * 32, y0 = blockIdx.y * 32;
#pragma unroll
    for (int r = 0; r < 4; r++)
        t[ty + r * 8][tx] = bs[(size_t)(y0 + ty + r * 8) * NN + x0 + tx];
    __syncthreads();
#pragma unroll
    for (int r = 0; r < 4; r++)
        g_bsT[(size_t)(x0 + ty + r * 8) * NN + y0 + tx] = t[tx][ty + r * 8];
}

// =============================================================================
// Kernel 3: product via bf16 mma, MULTI-TILE: A tile resident, 4 B-tiles
// per CTA with 2-stage pipelined ring. Epilogue: sigmoid -> 16-bit split.
// smem: [A_h 16K][A_l 16K][Bring: 2 x (B_h 16K, B_l 16K)] = 96 KB
// =============================================================================
#define PM_SMEM 98304

__global__ void __launch_bounds__(256, 2) product_mma()
{
    extern __shared__ __align__(1024) char dsm[];
    const uint32_t sm0 = smem_u32(dsm);

    const int tid  = threadIdx.x;
    const int lane = tid & 31;
    const int w    = tid >> 5;
    const int b    = blockIdx.z;
    const int m0   = blockIdx.y * 128;
    const int ng0  = blockIdx.x * 512;      // n-group base (4 tiles of 128)

    const int wi0 = (w >> 1) * 32;
    const int wm0 = (w & 1) * 64;

    const int ld_row = tid >> 3;
    const int ld_c   = tid & 7;

    const int a_row  = wi0 + (lane & 15);
    const int a_half = lane >> 4;
    const int b_nB   = (lane & 7) + ((lane >> 4) << 3);
    const int b_half = (lane >> 3) & 1;
    const int swz    = lane & 7;

    auto load_B = [&](int t) {
        const int n0t = ng0 + t * 128;
        const uint32_t sb = sm0 + 32768 + (t & 1) * 32768;
#pragma unroll
        for (int it = 0; it < 4; it++) {
            int row = ld_row + it * 32;
            uint32_t soff = row * 128 + ((ld_c ^ (row & 7)) * 16);
            size_t boff = ((size_t)b * NN + n0t + row) * 64 + ld_c * 8;
            cp16(sb + soff,         g_lh_h + boff);
            cp16(sb + 16384 + soff, g_lh_l + boff);
        }
        cp_commit();
    };

    // group 0: A tiles + B0
    {
#pragma unroll
        for (int it = 0; it < 4; it++) {
            int row = ld_row + it * 32;
            uint32_t soff = row * 128 + ((ld_c ^ (row & 7)) * 16);
            size_t aoff = ((size_t)b * NN + m0 + row) * 64 + ld_c * 8;
            cp16(sm0 + soff,         g_rh_h + aoff);
            cp16(sm0 + 16384 + soff, g_rh_l + aoff);
        }
        const uint32_t sb = sm0 + 32768;
#pragma unroll
        for (int it = 0; it < 4; it++) {
            int row = ld_row + it * 32;
            uint32_t soff = row * 128 + ((ld_c ^ (row & 7)) * 16);
            size_t boff = ((size_t)b * NN + ng0 + row) * 64 + ld_c * 8;
            cp16(sb + soff,         g_lh_h + boff);
            cp16(sb + 16384 + soff, g_lh_l + boff);
        }
        cp_commit();
    }
    load_B(1);   // group 1

#pragma unroll 1
    for (int t = 0; t < 4; t++) {
        cp_wait1();          // group t complete (allow newest 1 outstanding)
        __syncthreads();

        const uint32_t sbB = sm0 + 32768 + (t & 1) * 32768;

        float acc[2][8][4];
#pragma unroll
        for (int mt = 0; mt < 2; mt++)
#pragma unroll
            for (int j = 0; j < 8; j++)
#pragma unroll
                for (int q = 0; q < 4; q++) acc[mt][j][q] = 0.f;

#pragma unroll
        for (int ks = 0; ks < 4; ks++) {
            uint32_t ah[2][4], al[2][4];
#pragma unroll
            for (int mt = 0; mt < 2; mt++) {
                uint32_t off = (a_row + mt * 16) * 128 + (((2 * ks + a_half) ^ swz) * 16);
                LDSM_X4(ah[mt][0], ah[mt][1], ah[mt][2], ah[mt][3], sm0 + off);
                LDSM_X4(al[mt][0], al[mt][1], al[mt][2], al[mt][3], sm0 + 16384 + off);
            }
#pragma unroll
            for (int nt = 0; nt < 4; nt++) {
                uint32_t bh[4], bl[4];
                uint32_t off = (wm0 + nt * 16 + b_nB) * 128 + (((2 * ks + b_half) ^ swz) * 16);
                LDSM_X4(bh[0], bh[1], bh[2], bh[3], sbB + off);
                LDSM_X4(bl[0], bl[1], bl[2], bl[3], sbB + 16384 + off);
#pragma unroll
                for (int mt = 0; mt < 2; mt++) {
                    mma16816(acc[mt][nt * 2 + 0], ah[mt], bh[0], bh[1]);
                    mma16816(acc[mt][nt * 2 + 1], ah[mt], bh[2], bh[3]);
                    mma16816(acc[mt][nt * 2 + 0], ah[mt], bl[0], bl[1]);
                    mma16816(acc[mt][nt * 2 + 1], ah[mt], bl[2], bl[3]);
                    mma16816(acc[mt][nt * 2 + 0], al[mt], bh[0], bh[1]);
                    mma16816(acc[mt][nt * 2 + 1], al[mt], bh[2], bh[3]);
                }
            }
        }

        // epilogue for tile t
        const int n0t = ng0 + t * 128;
#pragma unroll
        for (int mt = 0; mt < 2; mt++) {
            int r0 = m0 + wi0 + mt * 16 + (lane >> 2);
#pragma unroll
            for (int nt = 0; nt < 4; nt++)
#pragma unroll
                for (int h = 0; h < 2; h++) {
                    int j = nt * 2 + h;
                    int cn = n0t + wm0 + nt * 16 + h * 8 + (lane & 3) * 2;
#pragma unroll
                    for (int rr = 0; rr < 2; rr++) {
                        int row = r0 + rr * 8;
                        float p0 = acc[mt][j][rr * 2 + 0];
                        float p1 = acc[mt][j][rr * 2 + 1];
                        float2 bb = *(const float2*)&g_bsT[(size_t)row * NN + cn];
                        float g0 = 1.f / (1.f + __expf(-(p0 + bb.x)));
                        float g1 = 1.f / (1.f + __expf(-(p1 + bb.y)));
                        uint32_t q0 = __float2uint_rn(g0 * 65535.f);
                        uint32_t q1 = __float2uint_rn(g1 * 65535.f);
                        size_t o = ((size_t)b << 20) + ((size_t)row << 10) + cn;
                        *(unsigned short*)&g_Gq_h[o] =
                            (unsigned short)((q0 >> 8) | ((q1 >> 8) << 8));
                        *(unsigned short*)&g_Gq_l[o] =
                            (unsigned short)((q0 & 255) | ((q1 & 255) << 8));
                    }
                }
        }

        __syncthreads();                 // all LDSM of stage t done before reuse
        if (t + 2 < 4) load_B(t + 2);
        else cp_commit();                // keep group count uniform
    }
}

// =============================================================================
// Kernel 4: int8 tensor-core GEMM, 512 threads, warp tile 32x32.
// S = s*c*(65536*Sum(VhGh) + 256*(Sum(VhGl)+Sum(VlGh)))   [VlGl dropped]
// 128x128 CTA tile, 4-stage ring (32 KB/stage). Term-grouped IMMA issue.
// Epilogue: exp(S) + per-CTA column partials.
// =============================================================================
#define GI_STAGES 4
#define GI_STAGE_BYTES 32768
#define GI_SMEM (GI_STAGES * GI_STAGE_BYTES)   // 128 KB

__global__ void __launch_bounds__(512, 1) gemm_i8(float* __restrict__ S)
{
    extern __shared__ __align__(1024) char dsm[];
    __shared__ float wsum[16][32];
    const uint32_t sm0 = smem_u32(dsm);

    const int tid  = threadIdx.x;
    const int lane = tid & 31;
    const int w    = tid >> 5;              // 0..15
    const int b    = blockIdx.z;
    const int i0g  = blockIdx.y * 128;
    const int m0   = blockIdx.x * 128;

    const int wi0 = (w >> 2) * 32;          // warp row block
    const int wm0 = (w & 3) * 32;           // warp col block

    const int a_row  = wi0 + (lane & 15);
    const int a_half = lane >> 4;
    const int aswz   = a_row & 3;
    const int b_nB   = (lane & 7) + ((lane >> 4) << 3);
    const int b_half = (lane >> 3) & 1;
    const int bswz   = b_nB & 3;

    int acc1[2][4][4], acc2[2][4][4];
#pragma unroll
    for (int mt = 0; mt < 2; mt++)
#pragma unroll
        for (int j = 0; j < 4; j++)
#pragma unroll
            for (int q = 0; q < 4; q++) { acc1[mt][j][q] = 0; acc2[mt][j][q] = 0; }

    const int ld_r = tid >> 2;              // 0..127
    const int ld_c = tid & 3;

    auto load_stage = [&](int kk) {
        const int k0 = kk * 64;
        const uint32_t sb = sm0 + (kk & 3) * GI_STAGE_BYTES;
        size_t aoff = (size_t)(i0g + ld_r) * 1024 + k0 + ld_c * 16;
        size_t boff = ((size_t)b << 20) + (size_t)(m0 + ld_r) * 1024 + k0 + ld_c * 16;
        uint32_t dsto = ld_r * 64 + ((ld_c ^ (ld_r & 3)) * 16);
        cp16(sb + dsto,         g_Vq_h + aoff);
        cp16(sb + 8192 + dsto,  g_Vq_l + aoff);
        cp16(sb + 16384 + dsto, g_Gq_h + boff);
        cp16(sb + 24576 + dsto, g_Gq_l + boff);
        cp_commit();
    };

    load_stage(0);
    load_stage(1);
    load_stage(2);

#pragma unroll 1
    for (int kk = 0; kk < 16; kk++) {
        if (kk + 3 < 16) load_stage(kk + 3);
        else cp_commit();
        cp_wait3();
        __syncthreads();

        const uint32_t sb = sm0 + (kk & 3) * GI_STAGE_BYTES;

#pragma unroll
        for (int ks = 0; ks < 2; ks++) {
            uint32_t ah[2][4], al[2][4];
#pragma unroll
            for (int mt = 0; mt < 2; mt++) {
                uint32_t off = (a_row + mt * 16) * 64
                             + (((2 * ks + a_half) ^ aswz) * 16);
                LDSM_X4(ah[mt][0], ah[mt][1], ah[mt][2], ah[mt][3], sb + off);
                LDSM_X4(al[mt][0], al[mt][1], al[mt][2], al[mt][3], sb + 8192 + off);
            }
            uint32_t bh[2][4], bl[2][4];
#pragma unroll
            for (int nt = 0; nt < 2; nt++) {
                uint32_t off = (wm0 + nt * 16 + b_nB) * 64
                             + (((2 * ks + b_half) ^ bswz) * 16);
                LDSM_X4(bh[nt][0], bh[nt][1], bh[nt][2], bh[nt][3], sb + 16384 + off);
                LDSM_X4(bl[nt][0], bl[nt][1], bl[nt][2], bl[nt][3], sb + 24576 + off);
            }
            // term-grouped issue: all independent within each group
#pragma unroll
            for (int mt = 0; mt < 2; mt++)
#pragma unroll
                for (int nt = 0; nt < 2; nt++) {
                    IMMA(acc1[mt][nt * 2 + 0], ah[mt], bh[nt][0], bh[nt][1]);
                    IMMA(acc1[mt][nt * 2 + 1], ah[mt], bh[nt][2], bh[nt][3]);
                }
#pragma unroll
            for (int mt = 0; mt < 2; mt++)
#pragma unroll
                for (int nt = 0; nt < 2; nt++) {
                    IMMA(acc2[mt][nt * 2 + 0], ah[mt], bl[nt][0], bl[nt][1]);
                    IMMA(acc2[mt][nt * 2 + 1], ah[mt], bl[nt][2], bl[nt][3]);
                }
#pragma unroll
            for (int mt = 0; mt < 2; mt++)
#pragma unroll
                for (int nt = 0; nt < 2; nt++) {
                    IMMA(acc2[mt][nt * 2 + 0], al[mt], bh[nt][0], bh[nt][1]);
                    IMMA(acc2[mt][nt * 2 + 1], al[mt], bh[nt][2], bh[nt][3]);
                }
        }
        __syncthreads();
    }

    // epilogue: S = sc1*acc1 + sc2*acc2; write exp(S) + column partials
    const float s_scale = __uint_as_float(g_vmax_u) * (1.f / 32639.f);
    const float base = s_scale * (1.f / 65535.f);
    const float sc1 = base * 65536.f;
    const float sc2 = base * 256.f;

    float cs[8];
#pragma unroll
    for (int i = 0; i < 8; i++) cs[i] = 0.f;

    float* Sb = S + ((size_t)b << 20);
#pragma unroll
    for (int mt = 0; mt < 2; mt++) {
        int r0 = i0g + wi0 + mt * 16 + (lane >> 2);
#pragma unroll
        for (int j = 0; j < 4; j++) {
            int cm = m0 + wm0 + j * 8 + (lane & 3) * 2;
            float v0 = fmaf(sc1, (float)acc1[mt][j][0], sc2 * (float)acc2[mt][j][0]);
            float v1 = fmaf(sc1, (float)acc1[mt][j][1], sc2 * (float)acc2[mt][j][1]);
            float v2 = fmaf(sc1, (float)acc1[mt][j][2], sc2 * (float)acc2[mt][j][2]);
            float v3 = fmaf(sc1, (float)acc1[mt][j][3], sc2 * (float)acc2[mt][j][3]);
            float e0 = __expf(v0), e1 = __expf(v1);
            float e2 = __expf(v2), e3 = __expf(v3);
            *(float2*)&Sb[((size_t)r0 << 10) + cm] = make_float2(e0, e1);
            *(float2*)&Sb[((size_t)(r0 + 8) << 10) + cm] = make_float2(e2, e3);
            cs[j * 2 + 0] += e0 + e2;
            cs[j * 2 + 1] += e1 + e3;
        }
    }
#pragma unroll
    for (int i = 0; i < 8; i++) {
        cs[i] += __shfl_xor_sync(0xffffffffu, cs[i], 4);
        cs[i] += __shfl_xor_sync(0xffffffffu, cs[i], 8);
        cs[i] += __shfl_xor_sync(0xffffffffu, cs[i], 16);
    }
    if (lane < 4) {
#pragma unroll
        for (int j = 0; j < 4; j++) {
            wsum[w][j * 8 + lane * 2 + 0] = cs[j * 2 + 0];
            wsum[w][j * 8 + lane * 2 + 1] = cs[j * 2 + 1];
        }
    }
    __syncthreads();
    if (tid < 128) {
        int blk = tid >> 5, c = tid & 31;
        float s = wsum[blk][c] + wsum[4 + blk][c] + wsum[8 + blk][c] + wsum[12 + blk][c];
        g_part[blockIdx.y][((size_t)b << 10) + m0 + blk * 32 + c] = s;
    }
}

// =============================================================================
// Kernel 5: reduce per-i-tile partials -> 1/colsum
// =============================================================================
__global__ __launch_bounds__(256) void reduce_part()
{
    int t = blockIdx.x * 256 + threadIdx.x;
    float s = 0.f;
#pragma unroll
    for (int q = 0; q < 8; q++) s += g_part[q][t];
    g_cinv[t] = __fdividef(1.f, s);
}

// =============================================================================
// Kernel 6: normalize in place: out = expS * (1/colsum)
// =============================================================================
__global__ __launch_bounds__(256) void normalize_kernel(float* __restrict__ S)
{
    const int bi = blockIdx.x;
    const int b = bi >> 10;
    const int m = threadIdx.x * 4;
    size_t base = (size_t)bi * NN + m;

    float4 v  = *(const float4*)&S[base];
    float4 iv = *(const float4*)&g_cinv[b * NN + m];
    float4 o;
    o.x = v.x * iv.x;
    o.y = v.y * iv.y;
    o.z = v.z * iv.z;
    o.w = v.w * iv.w;
    *(float4*)&S[base] = o;
}

// =============================================================================
extern "C" void kernel_launch(void* const* d_in, const int* in_sizes, int n_in,
                              void* d_out, int out_size)
{
    (void)in_sizes; (void)n_in; (void)out_size;
    const float* x  = (const float*)d_in[0];
    const float* W1 = (const float*)d_in[1];
    const float* W2 = (const float*)d_in[2];
    const float* W3 = (const float*)d_in[3];
    const float* bs = (const float*)d_in[4];
    const float* Vs = (const float*)d_in[5];
    float* out = (float*)d_out;

    cudaFuncSetAttribute(product_mma, cudaFuncAttributeMaxDynamicSharedMemorySize,
                         PM_SMEM);
    cudaFuncSetAttribute(gemm_i8, cudaFuncAttributeMaxDynamicSharedMemorySize,
                         GI_SMEM);

    prep_kernel<<<BB * NN, 64>>>(x, W1, W2, W3);
    zero_vmax<<<1, 1>>>();
    vmax_kernel<<<NN * NN / 1024, 256>>>(Vs);
    quant_vs<<<NN * NN / 1024, 256>>>(Vs);
    transpose_bs<<<dim3(32, 32), dim3(32, 8)>>>(bs);
    product_mma<<<dim3(2, 8, BB), 256, PM_SMEM>>>();
    gemm_i8<<<dim3(8, 8, BB), 512, GI_SMEM>>>(out);
    reduce_part<<<128, 256>>>();
    normalize_kernel<<<BB * NN, 256>>>(out);
}

// round 11
// speedup vs baseline: 2.9654x; 1.1278x over previous
#include <cuda_runtime.h>
#include <cuda_bf16.h>
#include <cstdint>

#define BB 32
#define NN 1024
#define TT 64

typedef unsigned long long ull;

// ---------------- scratch (device globals) -----------------------------------
__device__ __nv_bfloat16 g_lh_h[BB * NN * TT];            // 4 MB  lhs hi (b,n,t)
__device__ __nv_bfloat16 g_lh_l[BB * NN * TT];            // 4 MB  lhs lo
__device__ __nv_bfloat16 g_rh_h[BB * NN * TT];            // 4 MB  rhs hi (b,m,t)
__device__ __nv_bfloat16 g_rh_l[BB * NN * TT];            // 4 MB  rhs lo
// Tile-major, pre-swizzled operand blocks for the int8 GEMM.
// Vq block key (itile, kk):      16 KB = [h 8K][l 8K]
// Gq block key (b, mtile, kk):   16 KB = [h 8K][l 8K]
// in-plane addr = row*64 + (((k_chunk) ^ (row&3))*16) + (k&15)
__device__ __align__(128) unsigned char g_Vq[8 * 16 * 16384];                 // 2 MB
__device__ __align__(128) unsigned char g_Gq[(size_t)BB * 8 * 16 * 16384];    // 64 MB
__device__ float         g_bsT[NN * NN];                  // 4 MB  bs transposed
__device__ float         g_part[8][BB * NN];              // 1 MB  per-i-tile col partials
__device__ float         g_cinv[BB * NN];                 // per-(b,m) 1/colsum
__device__ unsigned int  g_vmax_u;                        // max|Vs| as float bits

// ---------------- smem / cp.async / mma helpers -------------------------------
__device__ __forceinline__ uint32_t smem_u32(const void* p) {
    uint32_t a;
    asm("{ .reg .u64 t; cvta.to.shared.u64 t, %1; cvt.u32.u64 %0, t; }"
        : "=r"(a) : "l"(p));
    return a;
}
__device__ __forceinline__ void cp16(uint32_t dst, const void* src) {
    asm volatile("cp.async.cg.shared.global [%0], [%1], 16;" :: "r"(dst), "l"(src));
}
__device__ __forceinline__ void cp_commit() {
    asm volatile("cp.async.commit_group;" ::: "memory");
}
__device__ __forceinline__ void cp_wait1() {
    asm volatile("cp.async.wait_group 1;" ::: "memory");
}
// ---- sm_90-level bulk copy + mbarrier (legal at base compute_100) ----
__device__ __forceinline__ void bulk_g2s(uint32_t dst, const void* src,
                                         uint32_t bytes, uint32_t mbar) {
    asm volatile(
        "cp.async.bulk.shared::cluster.global.mbarrier::complete_tx::bytes "
        "[%0], [%1], %2, [%3];"
        :: "r"(dst), "l"(src), "r"(bytes), "r"(mbar) : "memory");
}
__device__ __forceinline__ void mbar_init(uint32_t a, uint32_t n) {
    asm volatile("mbarrier.init.shared.b64 [%0], %1;" :: "r"(a), "r"(n) : "memory");
}
__device__ __forceinline__ void mbar_expect(uint32_t a, uint32_t tx) {
    asm volatile("mbarrier.arrive.expect_tx.shared.b64 _, [%0], %1;"
                 :: "r"(a), "r"(tx) : "memory");
}
#define MBAR_WAIT(mbar, parity) do {                                            \
    uint32_t _m = (mbar), _p = (parity), _done;                                 \
    asm volatile("{\n\t.reg .pred p;\n\t"                                       \
        "mbarrier.try_wait.parity.acquire.cta.shared::cta.b64 p, [%1], %2;\n\t" \
        "selp.b32 %0, 1, 0, p;\n\t}" : "=r"(_done) : "r"(_m), "r"(_p) : "memory"); \
    if (!_done) {                                                               \
        asm volatile("{\n\t.reg .pred P1;\n\t"                                  \
        "WAIT_LOOP_%=:\n\t"                                                     \
        "mbarrier.try_wait.parity.acquire.cta.shared::cta.b64 P1, [%0], %1;\n\t" \
        "@P1 bra.uni WAIT_DONE_%=;\n\tbra.uni WAIT_LOOP_%=;\n\tWAIT_DONE_%=:\n\t}" \
        :: "r"(_m), "r"(_p) : "memory");                                        \
    }                                                                           \
} while (0)

#define LDSM_X4(r0, r1, r2, r3, addr)                                           \
    asm volatile("ldmatrix.sync.aligned.m8n8.x4.shared.b16 {%0,%1,%2,%3}, [%4];" \
        : "=r"(r0), "=r"(r1), "=r"(r2), "=r"(r3) : "r"(addr))

__device__ __forceinline__ void mma16816(float* d, const uint32_t* a,
                                         uint32_t b0, uint32_t b1) {
    asm volatile(
        "mma.sync.aligned.m16n8k16.row.col.f32.bf16.bf16.f32 "
        "{%0,%1,%2,%3}, {%4,%5,%6,%7}, {%8,%9}, {%0,%1,%2,%3};"
        : "+f"(d[0]), "+f"(d[1]), "+f"(d[2]), "+f"(d[3])
        : "r"(a[0]), "r"(a[1]), "r"(a[2]), "r"(a[3]), "r"(b0), "r"(b1));
}
#define IMMA(d, a, b0, b1)                                                      \
    asm volatile(                                                               \
        "mma.sync.aligned.m16n8k32.row.col.s32.s8.u8.s32 "                      \
        "{%0,%1,%2,%3}, {%4,%5,%6,%7}, {%8,%9}, {%0,%1,%2,%3};"                 \
        : "+r"((d)[0]), "+r"((d)[1]), "+r"((d)[2]), "+r"((d)[3])                \
        : "r"((a)[0]), "r"((a)[1]), "r"((a)[2]), "r"((a)[3]), "r"(b0), "r"(b1))

// =============================================================================
// Kernel 1: prep — HBM-bound over 512 MB of x; writes bf16 hi/lo splits
// =============================================================================
__global__ __launch_bounds__(64) void prep_kernel(
    const float* __restrict__ x, const float* __restrict__ W1,
    const float* __restrict__ W2, const float* __restrict__ W3)
{
    __shared__ float sx[64][65];
    __shared__ float l1[64];
    __shared__ float sW1[64], sW3[64];

    const int t = threadIdx.x;
    sW1[t] = W1[t];
    sW3[t] = W3[t];

    const float4* x4 = reinterpret_cast<const float4*>(x) + (size_t)blockIdx.x * 1024;
#pragma unroll
    for (int i = 0; i < 16; i++) {
        int idx = i * 64 + t;
        float4 v = x4[idx];
        int f = idx >> 4;
        int c = (idx & 15) * 4;
        sx[f][c + 0] = v.x; sx[f][c + 1] = v.y;
        sx[f][c + 2] = v.z; sx[f][c + 3] = v.w;
    }
    __syncthreads();

    float acc = 0.f;
#pragma unroll
    for (int k = 0; k < 64; k++) acc += sx[t][k] * sW1[k];
    l1[t] = acc;

    float r = 0.f;
#pragma unroll
    for (int f = 0; f < 64; f++) r += sW3[f] * sx[f][t];

    __syncthreads();

    float l = 0.f;
#pragma unroll
    for (int f = 0; f < 64; f++) l += l1[f] * W2[f * 64 + t];

    size_t o = (size_t)blockIdx.x * 64 + t;
    __nv_bfloat16 lh = __float2bfloat16(l);
    __nv_bfloat16 rh = __float2bfloat16(r);
    g_lh_h[o] = lh;
    g_lh_l[o] = __float2bfloat16(l - __bfloat162float(lh));
    g_rh_h[o] = rh;
    g_rh_l[o] = __float2bfloat16(r - __bfloat162float(rh));
}

// =============================================================================
// Kernel 2: Vmax (deterministic) + quantize Vs into tile-major swizzled blocks
// =============================================================================
__global__ void zero_vmax() { g_vmax_u = 0u; }

__global__ __launch_bounds__(256) void vmax_kernel(const float* __restrict__ Vs)
{
    int i = (blockIdx.x * 256 + threadIdx.x) * 4;
    float4 v = *(const float4*)&Vs[i];
    float m = fmaxf(fmaxf(fabsf(v.x), fabsf(v.y)), fmaxf(fabsf(v.z), fabsf(v.w)));
#pragma unroll
    for (int s = 16; s > 0; s >>= 1)
        m = fmaxf(m, __shfl_xor_sync(0xffffffffu, m, s));
    if ((threadIdx.x & 31) == 0)
        atomicMax(&g_vmax_u, __float_as_uint(m));
}

__global__ __launch_bounds__(256) void quant_vs(const float* __restrict__ Vs)
{
    const float vmax = __uint_as_float(g_vmax_u);
    const float inv_s = 32639.f / fmaxf(vmax, 1e-30f);
    int e = (blockIdx.x * 256 + threadIdx.x) * 4;   // flat elem index, 4 consecutive k
    float4 v = *(const float4*)&Vs[e];
    uint32_t hp = 0, lp = 0;
    float vv[4] = {v.x, v.y, v.z, v.w};
#pragma unroll
    for (int j = 0; j < 4; j++) {
        int q = __float2int_rn(vv[j] * inv_s);
        q = max(-32768, min(32639, q));
        int vl = ((q + 128) & 255) - 128;
        int vh = (q - vl) >> 8;
        hp |= ((uint32_t)(vh & 255)) << (j * 8);
        lp |= ((uint32_t)(vl & 255)) << (j * 8);
    }
    int i = e >> 10;            // V row
    int k = e & 1023;           // V col (K dim), multiple of 4
    int itile = i >> 7, row = i & 127;
    int kk = k >> 6, kc = k & 63;
    int c = kc >> 4, byt = kc & 15;
    uint32_t blk = (uint32_t)(itile * 16 + kk) * 16384u;
    uint32_t off = blk + row * 64 + (((c ^ (row & 3))) * 16) + byt;
    *(uint32_t*)&g_Vq[off] = hp;            // h plane
    *(uint32_t*)&g_Vq[off + 8192] = lp;     // l plane
}

// =============================================================================
// Kernel 2d: transpose bias once
// =============================================================================
__global__ __launch_bounds__(256) void transpose_bs(const float* __restrict__ bs)
{
    __shared__ float t[32][33];
    const int tx = threadIdx.x, ty = threadIdx.y;
    const int x0 = blockIdx.x * 32, y0 = blockIdx.y * 32;
#pragma unroll
    for (int r = 0; r < 4; r++)
        t[ty + r * 8][tx] = bs[(size_t)(y0 + ty + r * 8) * NN + x0 + tx];
    __syncthreads();
#pragma unroll
    for (int r = 0; r < 4; r++)
        g_bsT[(size_t)(x0 + ty + r * 8) * NN + y0 + tx] = t[tx][ty + r * 8];
}

// =============================================================================
// Kernel 3: product via bf16 mma (A resident, 4 B-tiles pipelined).
// Epilogue: sigmoid -> 16-bit fixed point, written into the gemm's tile-major
// swizzled Gq block layout.
// =============================================================================
#define PM_SMEM 98304

__global__ void __launch_bounds__(256, 2) product_mma()
{
    extern __shared__ __align__(1024) char dsm[];
    const uint32_t sm0 = smem_u32(dsm);

    const int tid  = threadIdx.x;
    const int lane = tid & 31;
    const int w    = tid >> 5;
    const int b    = blockIdx.z;
    const int m0   = blockIdx.y * 128;
    const int ng0  = blockIdx.x * 512;

    const int wi0 = (w >> 1) * 32;
    const int wm0 = (w & 1) * 64;

    const int ld_row = tid >> 3;
    const int ld_c   = tid & 7;

    const int a_row  = wi0 + (lane & 15);
    const int a_half = lane >> 4;
    const int b_nB   = (lane & 7) + ((lane >> 4) << 3);
    const int b_half = (lane >> 3) & 1;
    const int swz    = lane & 7;

    auto load_B = [&](int t) {
        const int n0t = ng0 + t * 128;
        const uint32_t sb = sm0 + 32768 + (t & 1) * 32768;
#pragma unroll
        for (int it = 0; it < 4; it++) {
            int row = ld_row + it * 32;
            uint32_t soff = row * 128 + ((ld_c ^ (row & 7)) * 16);
            size_t boff = ((size_t)b * NN + n0t + row) * 64 + ld_c * 8;
            cp16(sb + soff,         g_lh_h + boff);
            cp16(sb + 16384 + soff, g_lh_l + boff);
        }
        cp_commit();
    };

    {
#pragma unroll
        for (int it = 0; it < 4; it++) {
            int row = ld_row + it * 32;
            uint32_t soff = row * 128 + ((ld_c ^ (row & 7)) * 16);
            size_t aoff = ((size_t)b * NN + m0 + row) * 64 + ld_c * 8;
            cp16(sm0 + soff,         g_rh_h + aoff);
            cp16(sm0 + 16384 + soff, g_rh_l + aoff);
        }
        const uint32_t sb = sm0 + 32768;
#pragma unroll
        for (int it = 0; it < 4; it++) {
            int row = ld_row + it * 32;
            uint32_t soff = row * 128 + ((ld_c ^ (row & 7)) * 16);
            size_t boff = ((size_t)b * NN + ng0 + row) * 64 + ld_c * 8;
            cp16(sb + soff,         g_lh_h + boff);
            cp16(sb + 16384 + soff, g_lh_l + boff);
        }
        cp_commit();
    }
    load_B(1);

#pragma unroll 1
    for (int t = 0; t < 4; t++) {
        cp_wait1();
        __syncthreads();

        const uint32_t sbB = sm0 + 32768 + (t & 1) * 32768;

        float acc[2][8][4];
#pragma unroll
        for (int mt = 0; mt < 2; mt++)
#pragma unroll
            for (int j = 0; j < 8; j++)
#pragma unroll
                for (int q = 0; q < 4; q++) acc[mt][j][q] = 0.f;

#pragma unroll
        for (int ks = 0; ks < 4; ks++) {
            uint32_t ah[2][4], al[2][4];
#pragma unroll
            for (int mt = 0; mt < 2; mt++) {
                uint32_t off = (a_row + mt * 16) * 128 + (((2 * ks + a_half) ^ swz) * 16);
                LDSM_X4(ah[mt][0], ah[mt][1], ah[mt][2], ah[mt][3], sm0 + off);
                LDSM_X4(al[mt][0], al[mt][1], al[mt][2], al[mt][3], sm0 + 16384 + off);
            }
#pragma unroll
            for (int nt = 0; nt < 4; nt++) {
                uint32_t bh[4], bl[4];
                uint32_t off = (wm0 + nt * 16 + b_nB) * 128 + (((2 * ks + b_half) ^ swz) * 16);
                LDSM_X4(bh[0], bh[1], bh[2], bh[3], sbB + off);
                LDSM_X4(bl[0], bl[1], bl[2], bl[3], sbB + 16384 + off);
#pragma unroll
                for (int mt = 0; mt < 2; mt++) {
                    mma16816(acc[mt][nt * 2 + 0], ah[mt], bh[0], bh[1]);
                    mma16816(acc[mt][nt * 2 + 1], ah[mt], bh[2], bh[3]);
                    mma16816(acc[mt][nt * 2 + 0], ah[mt], bl[0], bl[1]);
                    mma16816(acc[mt][nt * 2 + 1], ah[mt], bl[2], bl[3]);
                    mma16816(acc[mt][nt * 2 + 0], al[mt], bh[0], bh[1]);
                    mma16816(acc[mt][nt * 2 + 1], al[mt], bh[2], bh[3]);
                }
            }
        }

        // epilogue for tile t: sigmoid, 16-bit quantize, write into swizzled Gq
        const int n0t = ng0 + t * 128;
        const int mtile = m0 >> 7;   // m0 is 128-aligned
#pragma unroll
        for (int mt = 0; mt < 2; mt++) {
            int r0 = m0 + wi0 + mt * 16 + (lane >> 2);
#pragma unroll
            for (int nt = 0; nt < 4; nt++)
#pragma unroll
                for (int h = 0; h < 2; h++) {
                    int j = nt * 2 + h;
                    int cn = n0t + wm0 + nt * 16 + h * 8 + (lane & 3) * 2;
                    int kk = cn >> 6, kc = cn & 63;
                    int c = kc >> 4, byt = kc & 15;
#pragma unroll
                    for (int rr = 0; rr < 2; rr++) {
                        int row = r0 + rr * 8;
                        int rowt = row & 127;
                        float p0 = acc[mt][j][rr * 2 + 0];
                        float p1 = acc[mt][j][rr * 2 + 1];
                        float2 bb = *(const float2*)&g_bsT[(size_t)row * NN + cn];
                        float g0 = 1.f / (1.f + __expf(-(p0 + bb.x)));
                        float g1 = 1.f / (1.f + __expf(-(p1 + bb.y)));
                        uint32_t q0 = __float2uint_rn(g0 * 65535.f);
                        uint32_t q1 = __float2uint_rn(g1 * 65535.f);
                        size_t blk = ((size_t)((b * 8 + mtile) * 16 + kk)) * 16384u;
                        size_t off = blk + rowt * 64 + (((c ^ (rowt & 3))) * 16) + byt;
                        *(unsigned short*)&g_Gq[off] =
                            (unsigned short)((q0 >> 8) | ((q1 >> 8) << 8));
                        *(unsigned short*)&g_Gq[off + 8192] =
                            (unsigned short)((q0 & 255) | ((q1 & 255) << 8));
                    }
                }
        }

        __syncthreads();
        if (t + 2 < 4) load_B(t + 2);
        else cp_commit();
    }
}

// =============================================================================
// Kernel 4: int8 tensor-core GEMM fed by cp.async.bulk + mbarrier.
// 128x128 CTA tile, 256 threads, warp tile 32x64. 4-stage ring, 2 bulk copies
// per stage (A 16 KB, B 16 KB) issued by one thread.
// =============================================================================
#define GI_STAGE_BYTES 32768
#define GI_SMEM (4 * GI_STAGE_BYTES)   // 128 KB

__global__ void __launch_bounds__(256, 1) gemm_i8(float* __restrict__ S)
{
    extern __shared__ __align__(1024) char dsm[];
    __shared__ __align__(8) ull mbars[4];
    __shared__ float wsum[8][64];
    const uint32_t sm0 = smem_u32(dsm);
    const uint32_t mb0 = smem_u32(mbars);

    const int tid  = threadIdx.x;
    const int lane = tid & 31;
    const int w    = tid >> 5;
    const int b    = blockIdx.z;
    const int itile = blockIdx.y;
    const int mtile = blockIdx.x;
    const int i0g  = itile * 128;
    const int m0   = mtile * 128;

    const int wi0 = (w >> 1) * 32;
    const int wm0 = (w & 1) * 64;

    const int a_row  = wi0 + (lane & 15);
    const int a_half = lane >> 4;
    const int aswz   = a_row & 3;
    const int b_nB   = (lane & 7) + ((lane >> 4) << 3);
    const int b_half = (lane >> 3) & 1;
    const int bswz   = b_nB & 3;

    if (tid == 0) {
#pragma unroll
        for (int s = 0; s < 4; s++) mbar_init(mb0 + s * 8, 1);
    }
    __syncthreads();

    const unsigned char* srcA0 = g_Vq + (size_t)(itile * 16) * 16384u;
    const unsigned char* srcB0 = g_Gq + (size_t)((b * 8 + mtile) * 16) * 16384u;

    auto issue = [&](int kk) {
        int s = kk & 3;
        uint32_t mb = mb0 + s * 8;
        uint32_t sb = sm0 + s * GI_STAGE_BYTES;
        mbar_expect(mb, 32768);
        bulk_g2s(sb,         srcA0 + (size_t)kk * 16384u, 16384, mb);
        bulk_g2s(sb + 16384, srcB0 + (size_t)kk * 16384u, 16384, mb);
    };

    if (tid == 0) { issue(0); issue(1); issue(2); }

    int acc1[2][8][4], acc2[2][8][4];
#pragma unroll
    for (int mt = 0; mt < 2; mt++)
#pragma unroll
        for (int j = 0; j < 8; j++)
#pragma unroll
            for (int q = 0; q < 4; q++) { acc1[mt][j][q] = 0; acc2[mt][j][q] = 0; }

#pragma unroll 1
    for (int kk = 0; kk < 16; kk++) {
        if (tid == 0 && kk + 3 < 16) issue(kk + 3);
        MBAR_WAIT(mb0 + (kk & 3) * 8, (kk >> 2) & 1);

        const uint32_t sb = sm0 + (kk & 3) * GI_STAGE_BYTES;

#pragma unroll
        for (int ks = 0; ks < 2; ks++) {
            uint32_t ah[2][4], al[2][4];
#pragma unroll
            for (int mt = 0; mt < 2; mt++) {
                uint32_t off = (a_row + mt * 16) * 64
                             + (((2 * ks + a_half) ^ aswz) * 16);
                LDSM_X4(ah[mt][0], ah[mt][1], ah[mt][2], ah[mt][3], sb + off);
                LDSM_X4(al[mt][0], al[mt][1], al[mt][2], al[mt][3], sb + 8192 + off);
            }
            uint32_t bh[4][4], bl[4][4];
#pragma unroll
            for (int nt = 0; nt < 4; nt++) {
                uint32_t off = (wm0 + nt * 16 + b_nB) * 64
                             + (((2 * ks + b_half) ^ bswz) * 16);
                LDSM_X4(bh[nt][0], bh[nt][1], bh[nt][2], bh[nt][3], sb + 16384 + off);
                LDSM_X4(bl[nt][0], bl[nt][1], bl[nt][2], bl[nt][3], sb + 24576 + off);
            }
            // term-grouped issue (max RAW spacing on acc2)
#pragma unroll
            for (int mt = 0; mt < 2; mt++)
#pragma unroll
                for (int nt = 0; nt < 4; nt++) {
                    IMMA(acc1[mt][nt * 2 + 0], ah[mt], bh[nt][0], bh[nt][1]);
                    IMMA(acc1[mt][nt * 2 + 1], ah[mt], bh[nt][2], bh[nt][3]);
                }
#pragma unroll
            for (int mt = 0; mt < 2; mt++)
#pragma unroll
                for (int nt = 0; nt < 4; nt++) {
                    IMMA(acc2[mt][nt * 2 + 0], ah[mt], bl[nt][0], bl[nt][1]);
                    IMMA(acc2[mt][nt * 2 + 1], ah[mt], bl[nt][2], bl[nt][3]);
                }
#pragma unroll
            for (int mt = 0; mt < 2; mt++)
#pragma unroll
                for (int nt = 0; nt < 4; nt++) {
                    IMMA(acc2[mt][nt * 2 + 0], al[mt], bh[nt][0], bh[nt][1]);
                    IMMA(acc2[mt][nt * 2 + 1], al[mt], bh[nt][2], bh[nt][3]);
                }
        }
        __syncthreads();   // release stage buffer for reuse
    }

    // epilogue: S = sc1*acc1 + sc2*acc2; write exp(S) + column partials
    const float s_scale = __uint_as_float(g_vmax_u) * (1.f / 32639.f);
    const float base = s_scale * (1.f / 65535.f);
    const float sc1 = base * 65536.f;
    const float sc2 = base * 256.f;

    float cs[16];
#pragma unroll
    for (int i = 0; i < 16; i++) cs[i] = 0.f;

    float* Sb = S + ((size_t)b << 20);
#pragma unroll
    for (int mt = 0; mt < 2; mt++) {
        int r0 = i0g + wi0 + mt * 16 + (lane >> 2);
#pragma unroll
        for (int nt = 0; nt < 4; nt++)
#pragma unroll
            for (int h = 0; h < 2; h++) {
                int j = nt * 2 + h;
                int cm = m0 + wm0 + nt * 16 + h * 8 + (lane & 3) * 2;
                float v0 = fmaf(sc1, (float)acc1[mt][j][0], sc2 * (float)acc2[mt][j][0]);
                float v1 = fmaf(sc1, (float)acc1[mt][j][1], sc2 * (float)acc2[mt][j][1]);
                float v2 = fmaf(sc1, (float)acc1[mt][j][2], sc2 * (float)acc2[mt][j][2]);
                float v3 = fmaf(sc1, (float)acc1[mt][j][3], sc2 * (float)acc2[mt][j][3]);
                float e0 = __expf(v0), e1 = __expf(v1);
                float e2 = __expf(v2), e3 = __expf(v3);
                *(float2*)&Sb[((size_t)r0 << 10) + cm] = make_float2(e0, e1);
                *(float2*)&Sb[((size_t)(r0 + 8) << 10) + cm] = make_float2(e2, e3);
                cs[nt * 4 + h * 2 + 0] += e0 + e2;
                cs[nt * 4 + h * 2 + 1] += e1 + e3;
            }
    }
#pragma unroll
    for (int i = 0; i < 16; i++) {
        cs[i] += __shfl_xor_sync(0xffffffffu, cs[i], 4);
        cs[i] += __shfl_xor_sync(0xffffffffu, cs[i], 8);
        cs[i] += __shfl_xor_sync(0xffffffffu, cs[i], 16);
    }
    if (lane < 4) {
#pragma unroll
        for (int nt = 0; nt < 4; nt++)
#pragma unroll
            for (int h = 0; h < 2; h++) {
                wsum[w][nt * 16 + h * 8 + lane * 2 + 0] = cs[nt * 4 + h * 2 + 0];
                wsum[w][nt * 16 + h * 8 + lane * 2 + 1] = cs[nt * 4 + h * 2 + 1];
            }
    }
    __syncthreads();
    if (tid < 128) {
        int h = tid >> 6, c = tid & 63;
        float s = wsum[h][c] + wsum[2 + h][c] + wsum[4 + h][c] + wsum[6 + h][c];
        g_part[itile][((size_t)b << 10) + m0 + h * 64 + c] = s;
    }
}

// =============================================================================
// Kernel 5: reduce per-i-tile partials -> 1/colsum
// =============================================================================
__global__ __launch_bounds__(256) void reduce_part()
{
    int t = blockIdx.x * 256 + threadIdx.x;
    float s = 0.f;
#pragma unroll
    for (int q = 0; q < 8; q++) s += g_part[q][t];
    g_cinv[t] = __fdividef(1.f, s);
}

// =============================================================================
// Kernel 6: normalize in place: out = expS * (1/colsum)
// =============================================================================
__global__ __launch_bounds__(256) void normalize_kernel(float* __restrict__ S)
{
    const int bi = blockIdx.x;
    const int b = bi >> 10;
    const int m = threadIdx.x * 4;
    size_t base = (size_t)bi * NN + m;

    float4 v  = *(const float4*)&S[base];
    float4 iv = *(const float4*)&g_cinv[b * NN + m];
    float4 o;
    o.x = v.x * iv.x;
    o.y = v.y * iv.y;
    o.z = v.z * iv.z;
    o.w = v.w * iv.w;
    *(float4*)&S[base] = o;
}

// =============================================================================
extern "C" void kernel_launch(void* const* d_in, const int* in_sizes, int n_in,
                              void* d_out, int out_size)
{
    (void)in_sizes; (void)n_in; (void)out_size;
    const float* x  = (const float*)d_in[0];
    const float* W1 = (const float*)d_in[1];
    const float* W2 = (const float*)d_in[2];
    const float* W3 = (const float*)d_in[3];
    const float* bs = (const float*)d_in[4];
    const float* Vs = (const float*)d_in[5];
    float* out = (float*)d_out;

    cudaFuncSetAttribute(product_mma, cudaFuncAttributeMaxDynamicSharedMemorySize,
                         PM_SMEM);
    cudaFuncSetAttribute(gemm_i8, cudaFuncAttributeMaxDynamicSharedMemorySize,
                         GI_SMEM);

    prep_kernel<<<BB * NN, 64>>>(x, W1, W2, W3);
    zero_vmax<<<1, 1>>>();
    vmax_kernel<<<NN * NN / 1024, 256>>>(Vs);
    quant_vs<<<NN * NN / 1024, 256>>>(Vs);
    transpose_bs<<<dim3(32, 32), dim3(32, 8)>>>(bs);
    product_mma<<<dim3(2, 8, BB), 256, PM_SMEM>>>();
    gemm_i8<<<dim3(8, 8, BB), 256, GI_SMEM>>>(out);
    reduce_part<<<128, 256>>>();
    normalize_kernel<<<BB * NN, 256>>>(out);
}